// round 1
// baseline (speedup 1.0000x reference)
#include <cuda_runtime.h>
#include <math.h>

// ----------------------------------------------------------------------------
// Problem constants
// ----------------------------------------------------------------------------
#define BSZ   16
#define HIMG  64
#define WIMG  64
#define CH    256
#define NTOK  (BSZ*HIMG*WIMG)       // 65536
#define NHEAD 8
#define HS    32
#define PP    16                    // pooled grid side
#define NDTOK (BSZ*PP*PP)           // 4096

// ----------------------------------------------------------------------------
// Scratch (static __device__ arrays; no runtime allocation allowed)
// ----------------------------------------------------------------------------
__device__ float g_Q[NTOK*CH];
__device__ float g_K[NTOK*CH];
__device__ float g_V[NTOK*CH];
__device__ float g_CTX[NTOK*CH];
__device__ float g_S[3][NTOK*CH];
__device__ float g_edge[NTOK];
__device__ float g_wts[NTOK*3];
__device__ float g_xdl[NDTOK*CH];
__device__ float g_aQ[NDTOK*CH];
__device__ float g_aK[NDTOK*CH];
__device__ float g_aV[NDTOK*CH];
__device__ float g_xg[NDTOK*CH];
__device__ float g_Z[(size_t)NTOK*2*CH];

// ----------------------------------------------------------------------------
// Generic tiled fp32 GEMM: C[M,N] = A[M,K] @ B + bias
// transB==0: B is (K,N) row-major.  transB==1: B element [k,n] = Bm[n*K + k].
// Tiles: 64x64 output, K-tile 16, 256 threads, 4x4 per thread.
// ----------------------------------------------------------------------------
__global__ void gemm_kernel(const float* __restrict__ A,
                            const float* __restrict__ Bm,
                            const float* __restrict__ bias,
                            float* __restrict__ Cm,
                            int M, int N, int K, int transB)
{
    __shared__ float As[64][17];
    __shared__ float Bs[16][64];
    const int tid = threadIdx.x;
    const int tx = tid & 15, ty = tid >> 4;
    const int row0 = blockIdx.y * 64;
    const int col0 = blockIdx.x * 64;

    float acc[4][4] = {};

    for (int k0 = 0; k0 < K; k0 += 16) {
        // load A tile: 64 rows x 16 k
        #pragma unroll
        for (int i = tid; i < 64*16; i += 256) {
            int m = i >> 4, kk = i & 15;
            As[m][kk] = A[(size_t)(row0 + m) * K + (k0 + kk)];
        }
        // load B tile: 16 k x 64 n
        #pragma unroll
        for (int i = tid; i < 16*64; i += 256) {
            int kk = i >> 6, n = i & 63;
            Bs[kk][n] = transB ? Bm[(size_t)(col0 + n) * K + (k0 + kk)]
                               : Bm[(size_t)(k0 + kk) * N + (col0 + n)];
        }
        __syncthreads();
        #pragma unroll
        for (int kk = 0; kk < 16; kk++) {
            float a[4], b[4];
            #pragma unroll
            for (int i = 0; i < 4; i++) a[i] = As[ty*4 + i][kk];
            #pragma unroll
            for (int j = 0; j < 4; j++) b[j] = Bs[kk][tx*4 + j];
            #pragma unroll
            for (int i = 0; i < 4; i++)
                #pragma unroll
                for (int j = 0; j < 4; j++)
                    acc[i][j] += a[i] * b[j];
        }
        __syncthreads();
    }
    #pragma unroll
    for (int i = 0; i < 4; i++) {
        int r = row0 + ty*4 + i;
        #pragma unroll
        for (int j = 0; j < 4; j++) {
            int cidx = col0 + tx*4 + j;
            Cm[(size_t)r * N + cidx] = acc[i][j] + bias[cidx];
        }
    }
}

// ----------------------------------------------------------------------------
// Window attention core (per head, per window): scores/softmax/ctx.
// G windows per block so threads = G*WIN = 64 always. CTX written in
// un-windowed token layout so the out-projection is a flat GEMM.
// ----------------------------------------------------------------------------
template<int WS>
__global__ void winattn_kernel(const float* __restrict__ Q,
                               const float* __restrict__ K,
                               const float* __restrict__ V,
                               float* __restrict__ CTX)
{
    constexpr int WIN = WS*WS;
    constexpr int G   = 64 / WIN;
    constexpr int NW  = HIMG / WS;
    __shared__ float sQ[64][HS];
    __shared__ float sK[64][HS];
    __shared__ float sV[64][HS];

    const int t    = threadIdx.x;        // 64 threads
    const int head = blockIdx.y;
    const int g    = t / WIN;
    const int qi   = t % WIN;
    const int widx = blockIdx.x * G + g;
    const int b    = widx / (NW*NW);
    const int rem  = widx % (NW*NW);
    const int p1   = rem / NW, p2 = rem % NW;
    const int r    = p1*WS + qi/WS;
    const int cc   = p2*WS + qi%WS;
    const int token = (b*HIMG + r)*WIMG + cc;
    const size_t base = (size_t)token*CH + head*HS;

    #pragma unroll
    for (int d = 0; d < HS; d++) {
        sQ[t][d] = Q[base + d];
        sK[t][d] = K[base + d];
        sV[t][d] = V[base + d];
    }
    __syncthreads();

    const float scale = 0.17677669529663687f;   // 1/sqrt(32)
    float sc[WIN];
    float mx = -1e30f;
    #pragma unroll
    for (int v = 0; v < WIN; v++) {
        float dot = 0.f;
        #pragma unroll
        for (int d = 0; d < HS; d++) dot += sQ[t][d] * sK[g*WIN + v][d];
        dot *= scale;
        sc[v] = dot;
        mx = fmaxf(mx, dot);
    }
    float sum = 0.f;
    #pragma unroll
    for (int v = 0; v < WIN; v++) { sc[v] = expf(sc[v] - mx); sum += sc[v]; }
    const float inv = 1.f / sum;

    #pragma unroll
    for (int d = 0; d < HS; d++) {
        float a = 0.f;
        #pragma unroll
        for (int v = 0; v < WIN; v++) a += sc[v] * sV[g*WIN + v][d];
        CTX[base + d] = a * inv;
    }
}

// ----------------------------------------------------------------------------
// Edge conv: edge[b,y,x] = | sum_{c,ky,kx} x[b,y+ky-1,x+kx-1,c] * w[c,ky,kx] |
// One block per pixel, 256 threads over channels, deterministic shfl reduce.
// ----------------------------------------------------------------------------
__global__ void edge_kernel(const float* __restrict__ x,
                            const float* __restrict__ ew,
                            float* __restrict__ edge)
{
    __shared__ float sw[CH*9];
    __shared__ float red[8];
    const int pix = blockIdx.x;
    const int b = pix >> 12, y = (pix >> 6) & 63, xx = pix & 63;
    const int c = threadIdx.x;
    for (int i = c; i < CH*9; i += 256) sw[i] = ew[i];
    __syncthreads();

    float acc = 0.f;
    #pragma unroll
    for (int ky = 0; ky < 3; ky++) {
        int yy = y + ky - 1;
        if (yy < 0 || yy > 63) continue;
        #pragma unroll
        for (int kx = 0; kx < 3; kx++) {
            int xw = xx + kx - 1;
            if (xw < 0 || xw > 63) continue;
            acc += x[((size_t)((b*64 + yy)*64 + xw))*CH + c] * sw[c*9 + ky*3 + kx];
        }
    }
    #pragma unroll
    for (int o = 16; o; o >>= 1) acc += __shfl_xor_sync(0xffffffffu, acc, o);
    if ((c & 31) == 0) red[c >> 5] = acc;
    __syncthreads();
    if (c == 0) {
        float tsum = 0.f;
        #pragma unroll
        for (int i = 0; i < 8; i++) tsum += red[i];
        edge[pix] = fabsf(tsum);
    }
}

// ----------------------------------------------------------------------------
// 3x3 avgpool (SAME, /9) + tiny MLP + softmax -> per-pixel scale weights
// ----------------------------------------------------------------------------
__global__ void wts_kernel(const float* __restrict__ edge,
                           const float* __restrict__ w1, const float* __restrict__ b1,
                           const float* __restrict__ w2, const float* __restrict__ b2,
                           float* __restrict__ wts)
{
    int pix = blockIdx.x * blockDim.x + threadIdx.x;
    if (pix >= NTOK) return;
    int b = pix >> 12, y = (pix >> 6) & 63, xx = pix & 63;
    float s = 0.f;
    for (int dy = -1; dy <= 1; dy++) {
        int yy = y + dy; if (yy < 0 || yy > 63) continue;
        for (int dx = -1; dx <= 1; dx++) {
            int xw = xx + dx; if (xw < 0 || xw > 63) continue;
            s += edge[(b*64 + yy)*64 + xw];
        }
    }
    float e = s * (1.f/9.f);
    float lg[3] = {b2[0], b2[1], b2[2]};
    #pragma unroll
    for (int j = 0; j < 16; j++) {
        float h = fmaxf(e * w1[j] + b1[j], 0.f);
        lg[0] += h * w2[j*3 + 0];
        lg[1] += h * w2[j*3 + 1];
        lg[2] += h * w2[j*3 + 2];
    }
    float mx = fmaxf(lg[0], fmaxf(lg[1], lg[2]));
    float e0 = expf(lg[0]-mx), e1 = expf(lg[1]-mx), e2 = expf(lg[2]-mx);
    float inv = 1.f / (e0 + e1 + e2);
    wts[pix*3+0] = e0*inv;
    wts[pix*3+1] = e1*inv;
    wts[pix*3+2] = e2*inv;
}

// ----------------------------------------------------------------------------
// DlightConv: mean over 4x4 block of S1, logits = mean @ dl_w + dl_b,
// softmax over 16, x_dl = sum_w S1 * prob. One block per (b,p1,p2).
// ----------------------------------------------------------------------------
__global__ void dlight_kernel(const float* __restrict__ S1,
                              const float* __restrict__ dlw,
                              const float* __restrict__ dlb,
                              float* __restrict__ xdl)
{
    __shared__ float part[8][16];
    __shared__ float probs[16];
    const int bx = blockIdx.x;                 // 0..4095
    const int b = bx >> 8, p1 = (bx >> 4) & 15, p2 = bx & 15;
    const int c = threadIdx.x;

    float vals[16];
    float mean = 0.f;
    #pragma unroll
    for (int wi = 0; wi < 16; wi++) {
        int r = p1*4 + (wi >> 2), cc = p2*4 + (wi & 3);
        vals[wi] = S1[((size_t)((b*64 + r)*64 + cc))*CH + c];
        mean += vals[wi];
    }
    mean *= (1.f/16.f);

    float contrib[16];
    #pragma unroll
    for (int j = 0; j < 16; j++) contrib[j] = mean * dlw[c*16 + j];
    #pragma unroll
    for (int j = 0; j < 16; j++)
        #pragma unroll
        for (int o = 16; o; o >>= 1)
            contrib[j] += __shfl_xor_sync(0xffffffffu, contrib[j], o);
    if ((c & 31) == 0) {
        #pragma unroll
        for (int j = 0; j < 16; j++) part[c >> 5][j] = contrib[j];
    }
    __syncthreads();
    if (c == 0) {
        float lg[16], mx = -1e30f;
        #pragma unroll
        for (int j = 0; j < 16; j++) {
            float v = dlb[j];
            #pragma unroll
            for (int w = 0; w < 8; w++) v += part[w][j];
            lg[j] = v;
            mx = fmaxf(mx, v);
        }
        float sum = 0.f;
        #pragma unroll
        for (int j = 0; j < 16; j++) { lg[j] = expf(lg[j] - mx); sum += lg[j]; }
        float inv = 1.f / sum;
        #pragma unroll
        for (int j = 0; j < 16; j++) probs[j] = lg[j] * inv;
    }
    __syncthreads();
    float acc = 0.f;
    #pragma unroll
    for (int wi = 0; wi < 16; wi++) acc += vals[wi] * probs[wi];
    xdl[(size_t)bx*CH + c] = acc;
}

// ----------------------------------------------------------------------------
// Axial attention (16x16 pooled grid, full-C, gaussian bias, no scaling).
// axis==0: one block per (b, row);  axis==1: one block per (b, col), += out.
// ----------------------------------------------------------------------------
__global__ void axial_kernel(const float* __restrict__ Q,
                             const float* __restrict__ K,
                             const float* __restrict__ V,
                             const float* __restrict__ gsp,
                             const float* __restrict__ gbp,
                             float* __restrict__ out,
                             int axis)
{
    __shared__ float sQ[16][CH];
    __shared__ float sK[16][CH];
    __shared__ float sc[16][17];
    const int blk = blockIdx.x;          // 0..255
    const int b = blk >> 4, f = blk & 15;
    const int t = threadIdx.x;           // 256

    for (int idx = t; idx < 16*CH; idx += 256) {
        int i = idx >> 8, c = idx & 255;
        size_t tok = (axis == 0) ? (size_t)((b*16 + f)*16 + i)
                                 : (size_t)((b*16 + i)*16 + f);
        sQ[i][c] = Q[tok*CH + c];
        sK[i][c] = K[tok*CH + c];
    }
    __syncthreads();

    {   // scores: thread (w,v)
        int w = t >> 4, v = t & 15;
        float dot = 0.f;
        #pragma unroll 8
        for (int c = 0; c < CH; c++) dot += sQ[w][c] * sK[v][c];
        float gs = gsp[0], gb0 = gbp[0];
        float d2 = (float)((v - w) * (v - w));
        sc[w][v] = dot - (gs * d2 + gb0);
    }
    __syncthreads();
    if (t < 16) {
        float mx = -1e30f;
        #pragma unroll
        for (int v = 0; v < 16; v++) mx = fmaxf(mx, sc[t][v]);
        float sum = 0.f;
        #pragma unroll
        for (int v = 0; v < 16; v++) { float e = expf(sc[t][v] - mx); sc[t][v] = e; sum += e; }
        float inv = 1.f / sum;
        #pragma unroll
        for (int v = 0; v < 16; v++) sc[t][v] *= inv;
    }
    __syncthreads();

    // ctx: thread d computes all 16 query outputs for its channel
    const int d = t;
    float acc[16] = {};
    #pragma unroll
    for (int v = 0; v < 16; v++) {
        size_t tokv = (axis == 0) ? (size_t)((b*16 + f)*16 + v)
                                  : (size_t)((b*16 + v)*16 + f);
        float vv = V[tokv*CH + d];
        #pragma unroll
        for (int w = 0; w < 16; w++) acc[w] += sc[w][v] * vv;
    }
    #pragma unroll
    for (int w = 0; w < 16; w++) {
        size_t tokw = (axis == 0) ? (size_t)((b*16 + f)*16 + w)
                                  : (size_t)((b*16 + w)*16 + f);
        if (axis == 0) out[tokw*CH + d] = acc[w];
        else           out[tokw*CH + d] += acc[w];
    }
}

// ----------------------------------------------------------------------------
// Build Z[token, 0:256]   = bilinear-upsampled x_g (align_corners, 16->64)
//       Z[token, 256:512] = sum_i wts_i * S_i   (blended h_map)
// ----------------------------------------------------------------------------
__global__ void zbuild_kernel(const float* __restrict__ xg,
                              const float* __restrict__ S0,
                              const float* __restrict__ S1,
                              const float* __restrict__ S2,
                              const float* __restrict__ wts,
                              float* __restrict__ Z)
{
    const int pix = blockIdx.x;
    const int c = threadIdx.x;
    const int b = pix >> 12, y = (pix >> 6) & 63, xx = pix & 63;
    const float scl = 15.f / 63.f;

    float pr = y * scl;
    int r0 = (int)floorf(pr);
    float tr = pr - (float)r0;
    int r1 = min(r0 + 1, 15);
    float pc = xx * scl;
    int c0 = (int)floorf(pc);
    float tc = pc - (float)c0;
    int c1 = min(c0 + 1, 15);

    size_t base = (size_t)b * 256;   // b*16*16
    float v00 = xg[(base + r0*16 + c0)*CH + c];
    float v01 = xg[(base + r0*16 + c1)*CH + c];
    float v10 = xg[(base + r1*16 + c0)*CH + c];
    float v11 = xg[(base + r1*16 + c1)*CH + c];
    float left  = v00*(1.f-tr) + v10*tr;
    float right = v01*(1.f-tr) + v11*tr;
    float interp = left*(1.f-tc) + right*tc;

    size_t zb = (size_t)pix*512;
    Z[zb + c] = interp;

    float w0 = wts[pix*3+0], w1 = wts[pix*3+1], w2 = wts[pix*3+2];
    size_t sb = (size_t)pix*CH + c;
    Z[zb + 256 + c] = w0*S0[sb] + w1*S1[sb] + w2*S2[sb];
}

// ----------------------------------------------------------------------------
// Host launch
// ----------------------------------------------------------------------------
extern "C" void kernel_launch(void* const* d_in, const int* in_sizes, int n_in,
                              void* d_out, int out_size)
{
    const float* x      = (const float*)d_in[0];
    const float* attn_w = (const float*)d_in[1];
    const float* attn_b = (const float*)d_in[2];
    const float* edge_w = (const float*)d_in[3];
    const float* mlp_w1 = (const float*)d_in[4];
    const float* mlp_b1 = (const float*)d_in[5];
    const float* mlp_w2 = (const float*)d_in[6];
    const float* mlp_b2 = (const float*)d_in[7];
    const float* dl_w   = (const float*)d_in[8];
    const float* dl_b   = (const float*)d_in[9];
    const float* ax_w   = (const float*)d_in[10];
    const float* ax_b   = (const float*)d_in[11];
    const float* g_sh   = (const float*)d_in[12];
    const float* g_bi   = (const float*)d_in[13];
    const float* sq_w   = (const float*)d_in[14];
    const float* sq_b   = (const float*)d_in[15];
    float* out = (float*)d_out;

    float *Qb, *Kb, *Vb, *CTXb, *Sb, *EDGEb, *WTSb, *XDLb, *AQb, *AKb, *AVb, *XGb, *Zb;
    cudaGetSymbolAddress((void**)&Qb,   g_Q);
    cudaGetSymbolAddress((void**)&Kb,   g_K);
    cudaGetSymbolAddress((void**)&Vb,   g_V);
    cudaGetSymbolAddress((void**)&CTXb, g_CTX);
    cudaGetSymbolAddress((void**)&Sb,   g_S);
    cudaGetSymbolAddress((void**)&EDGEb,g_edge);
    cudaGetSymbolAddress((void**)&WTSb, g_wts);
    cudaGetSymbolAddress((void**)&XDLb, g_xdl);
    cudaGetSymbolAddress((void**)&AQb,  g_aQ);
    cudaGetSymbolAddress((void**)&AKb,  g_aK);
    cudaGetSymbolAddress((void**)&AVb,  g_aV);
    cudaGetSymbolAddress((void**)&XGb,  g_xg);
    cudaGetSymbolAddress((void**)&Zb,   g_Z);

    const dim3 gemm_grid_big(CH/64, NTOK/64);     // (4, 1024)
    const dim3 gemm_grid_small(CH/64, NDTOK/64);  // (4, 64)
    const dim3 attn_grid(1024, NHEAD);

    // ---- 3 window-attention branches ----
    for (int br = 0; br < 3; br++) {
        const float* Wq = attn_w + (size_t)(br*4 + 0)*CH*CH;
        const float* Wk = attn_w + (size_t)(br*4 + 1)*CH*CH;
        const float* Wv = attn_w + (size_t)(br*4 + 2)*CH*CH;
        const float* Wo = attn_w + (size_t)(br*4 + 3)*CH*CH;
        const float* bq = attn_b + (br*4 + 0)*CH;
        const float* bk = attn_b + (br*4 + 1)*CH;
        const float* bv = attn_b + (br*4 + 2)*CH;
        const float* bo = attn_b + (br*4 + 3)*CH;

        gemm_kernel<<<gemm_grid_big, 256>>>(x, Wq, bq, Qb, NTOK, CH, CH, 0);
        gemm_kernel<<<gemm_grid_big, 256>>>(x, Wk, bk, Kb, NTOK, CH, CH, 0);
        gemm_kernel<<<gemm_grid_big, 256>>>(x, Wv, bv, Vb, NTOK, CH, CH, 0);

        if (br == 0)      winattn_kernel<2><<<attn_grid, 64>>>(Qb, Kb, Vb, CTXb);
        else if (br == 1) winattn_kernel<4><<<attn_grid, 64>>>(Qb, Kb, Vb, CTXb);
        else              winattn_kernel<8><<<attn_grid, 64>>>(Qb, Kb, Vb, CTXb);

        gemm_kernel<<<gemm_grid_big, 256>>>(CTXb, Wo, bo, Sb + (size_t)br*NTOK*CH,
                                            NTOK, CH, CH, 0);
    }

    // ---- edge selector ----
    edge_kernel<<<NTOK, 256>>>(x, edge_w, EDGEb);
    wts_kernel<<<NTOK/256, 256>>>(EDGEb, mlp_w1, mlp_b1, mlp_w2, mlp_b2, WTSb);

    // ---- DlightConv pooling (reuses ws=4 branch output S[1]) ----
    dlight_kernel<<<NDTOK, 256>>>(Sb + (size_t)1*NTOK*CH, dl_w, dl_b, XDLb);

    // ---- axial q,k,v projections ----
    gemm_kernel<<<gemm_grid_small, 256>>>(XDLb, ax_w + 0*CH*CH, ax_b + 0*CH, AQb, NDTOK, CH, CH, 0);
    gemm_kernel<<<gemm_grid_small, 256>>>(XDLb, ax_w + 1*CH*CH, ax_b + 1*CH, AKb, NDTOK, CH, CH, 0);
    gemm_kernel<<<gemm_grid_small, 256>>>(XDLb, ax_w + 2*CH*CH, ax_b + 2*CH, AVb, NDTOK, CH, CH, 0);

    // ---- axial attention: rows (write) then columns (accumulate) ----
    axial_kernel<<<BSZ*PP, 256>>>(AQb, AKb, AVb, g_sh, g_bi, XGb, 0);
    axial_kernel<<<BSZ*PP, 256>>>(AQb, AKb, AVb, g_sh, g_bi, XGb, 1);

    // ---- build concat matrix Z (upsample + blend) and final projection ----
    zbuild_kernel<<<NTOK, 256>>>(XGb,
                                 Sb + (size_t)0*NTOK*CH,
                                 Sb + (size_t)1*NTOK*CH,
                                 Sb + (size_t)2*NTOK*CH,
                                 WTSb, Zb);

    gemm_kernel<<<gemm_grid_big, 256>>>(Zb, sq_w, sq_b, out, NTOK, CH, 2*CH, 1);
}

// round 2
// speedup vs baseline: 2.3927x; 2.3927x over previous
#include <cuda_runtime.h>
#include <math.h>

// ----------------------------------------------------------------------------
// Problem constants
// ----------------------------------------------------------------------------
#define BSZ   16
#define HIMG  64
#define WIMG  64
#define CH    256
#define NTOK  (BSZ*HIMG*WIMG)       // 65536
#define NHEAD 8
#define HS    32
#define PP    16
#define NDTOK (BSZ*PP*PP)           // 4096

// ----------------------------------------------------------------------------
// Scratch
// ----------------------------------------------------------------------------
__device__ float g_Q[NTOK*CH];
__device__ float g_K[NTOK*CH];
__device__ float g_V[NTOK*CH];
__device__ float g_CTX[NTOK*CH];
__device__ float g_S[3][NTOK*CH];
__device__ float g_t9[NTOK*9];
__device__ float g_edge[NTOK];
__device__ float g_wts[NTOK*3];
__device__ float g_xdl[NDTOK*CH];
__device__ float g_aQ[NDTOK*CH];
__device__ float g_aK[NDTOK*CH];
__device__ float g_aV[NDTOK*CH];
__device__ float g_xg[NDTOK*CH];
__device__ float g_Z[(size_t)NTOK*2*CH];

// ----------------------------------------------------------------------------
// 128x128x8 double-buffered fp32 GEMM, 256 threads, 8x8 per thread.
// C[M,N] = A[M,K] @ B + bias.   transB==0: B is (K,N).  transB==1: B[n*K+k].
// ----------------------------------------------------------------------------
__global__ __launch_bounds__(256)
void gemm128(const float* __restrict__ A, const float* __restrict__ Bm,
             const float* __restrict__ bias, float* __restrict__ Cm,
             int M, int N, int K, int transB)
{
    __shared__ float As[2][8][132];
    __shared__ float Bs[2][8][132];
    const int tid = threadIdx.x;
    const int tx = tid & 15, ty = tid >> 4;
    const int row0 = blockIdx.y * 128, col0 = blockIdx.x * 128;

    const int ar = tid >> 1, ah = (tid & 1) * 4;      // A loader: row, k-offset
    const int bk = tid >> 5, bn = (tid & 31) * 4;     // B loader (transB=0)
    const int brw = tid >> 1, bh = (tid & 1) * 4;     // B loader (transB=1)

    float4 areg = *(const float4*)(A + (size_t)(row0 + ar) * K + ah);
    float4 breg;
    if (!transB) breg = *(const float4*)(Bm + (size_t)bk * N + col0 + bn);
    else         breg = *(const float4*)(Bm + (size_t)(col0 + brw) * K + bh);

    As[0][ah+0][ar] = areg.x; As[0][ah+1][ar] = areg.y;
    As[0][ah+2][ar] = areg.z; As[0][ah+3][ar] = areg.w;
    if (!transB) {
        *(float4*)&Bs[0][bk][bn] = breg;
    } else {
        Bs[0][bh+0][brw] = breg.x; Bs[0][bh+1][brw] = breg.y;
        Bs[0][bh+2][brw] = breg.z; Bs[0][bh+3][brw] = breg.w;
    }
    __syncthreads();

    float acc[8][8] = {};
    const int nt = K >> 3;
    int p = 0;

    for (int t = 0; t < nt; t++) {
        if (t + 1 < nt) {
            const int k0 = (t + 1) << 3;
            areg = *(const float4*)(A + (size_t)(row0 + ar) * K + k0 + ah);
            if (!transB) breg = *(const float4*)(Bm + (size_t)(k0 + bk) * N + col0 + bn);
            else         breg = *(const float4*)(Bm + (size_t)(col0 + brw) * K + k0 + bh);
        }
        #pragma unroll
        for (int kk = 0; kk < 8; kk++) {
            float4 a0 = *(const float4*)&As[p][kk][ty*4];
            float4 a1 = *(const float4*)&As[p][kk][64 + ty*4];
            float4 b0 = *(const float4*)&Bs[p][kk][tx*4];
            float4 b1 = *(const float4*)&Bs[p][kk][64 + tx*4];
            float av[8] = {a0.x,a0.y,a0.z,a0.w,a1.x,a1.y,a1.z,a1.w};
            float bv[8] = {b0.x,b0.y,b0.z,b0.w,b1.x,b1.y,b1.z,b1.w};
            #pragma unroll
            for (int i = 0; i < 8; i++)
                #pragma unroll
                for (int j = 0; j < 8; j++)
                    acc[i][j] += av[i] * bv[j];
        }
        if (t + 1 < nt) {
            p ^= 1;
            As[p][ah+0][ar] = areg.x; As[p][ah+1][ar] = areg.y;
            As[p][ah+2][ar] = areg.z; As[p][ah+3][ar] = areg.w;
            if (!transB) {
                *(float4*)&Bs[p][bk][bn] = breg;
            } else {
                Bs[p][bh+0][brw] = breg.x; Bs[p][bh+1][brw] = breg.y;
                Bs[p][bh+2][brw] = breg.z; Bs[p][bh+3][brw] = breg.w;
            }
            __syncthreads();
        }
    }

    const float4 bias0 = *(const float4*)&bias[col0 + tx*4];
    const float4 bias1 = *(const float4*)&bias[col0 + 64 + tx*4];
    #pragma unroll
    for (int i = 0; i < 8; i++) {
        const int r = row0 + ((i < 4) ? (ty*4 + i) : (64 + ty*4 + i - 4));
        float4 o;
        o.x = acc[i][0] + bias0.x; o.y = acc[i][1] + bias0.y;
        o.z = acc[i][2] + bias0.z; o.w = acc[i][3] + bias0.w;
        *(float4*)&Cm[(size_t)r * N + col0 + tx*4] = o;
        o.x = acc[i][4] + bias1.x; o.y = acc[i][5] + bias1.y;
        o.z = acc[i][6] + bias1.z; o.w = acc[i][7] + bias1.w;
        *(float4*)&Cm[(size_t)r * N + col0 + 64 + tx*4] = o;
    }
}

// ----------------------------------------------------------------------------
// Window attention: 128 threads = 64 tokens x 2 heads, q in regs, K/V in smem.
// ----------------------------------------------------------------------------
template<int WS>
__global__ __launch_bounds__(128)
void winattn_kernel(const float4* __restrict__ Q4,
                    const float4* __restrict__ K4,
                    const float4* __restrict__ V4,
                    float4* __restrict__ CTX4)
{
    constexpr int WIN = WS*WS;
    constexpr int G   = 64 / WIN;
    constexpr int NW  = HIMG / WS;
    __shared__ float4 sK[2][64][9];
    __shared__ float4 sV[2][64][9];

    const int t    = threadIdx.x;
    const int slot = t >> 6;
    const int tt   = t & 63;
    const int head = blockIdx.y * 2 + slot;
    const int g    = tt / WIN;
    const int qi   = tt % WIN;
    const int widx = blockIdx.x * G + g;
    const int b    = widx / (NW*NW);
    const int rem  = widx % (NW*NW);
    const int p1   = rem / NW, p2 = rem % NW;
    const int r    = p1*WS + qi/WS;
    const int cc   = p2*WS + qi%WS;
    const int token = (b*HIMG + r)*WIMG + cc;
    const size_t base4 = (size_t)token*(CH/4) + head*(HS/4);   // float4 units

    float4 q[8];
    #pragma unroll
    for (int d = 0; d < 8; d++) {
        q[d]            = Q4[base4 + d];
        sK[slot][tt][d] = K4[base4 + d];
        sV[slot][tt][d] = V4[base4 + d];
    }
    __syncthreads();

    const float scale = 0.17677669529663687f;   // 1/sqrt(32)
    float sc[WIN];
    float mx = -1e30f;
    #pragma unroll
    for (int v = 0; v < WIN; v++) {
        float dot = 0.f;
        #pragma unroll
        for (int d = 0; d < 8; d++) {
            float4 k4 = sK[slot][g*WIN + v][d];
            dot += q[d].x*k4.x + q[d].y*k4.y + q[d].z*k4.z + q[d].w*k4.w;
        }
        dot *= scale;
        sc[v] = dot;
        mx = fmaxf(mx, dot);
    }
    float sum = 0.f;
    #pragma unroll
    for (int v = 0; v < WIN; v++) { sc[v] = expf(sc[v] - mx); sum += sc[v]; }
    const float inv = 1.f / sum;
    #pragma unroll
    for (int v = 0; v < WIN; v++) sc[v] *= inv;

    #pragma unroll
    for (int d = 0; d < 8; d++) {
        float4 a = make_float4(0.f, 0.f, 0.f, 0.f);
        #pragma unroll
        for (int v = 0; v < WIN; v++) {
            float4 vv = sV[slot][g*WIN + v][d];
            a.x += sc[v]*vv.x; a.y += sc[v]*vv.y;
            a.z += sc[v]*vv.z; a.w += sc[v]*vv.w;
        }
        CTX4[base4 + d] = a;
    }
}

// ----------------------------------------------------------------------------
// Edge conv stage 1: t9[pix,k] = sum_c x[pix,c] * w[c,k]   (warp per pixel)
// ----------------------------------------------------------------------------
__global__ void conv9_kernel(const float* __restrict__ x,
                             const float* __restrict__ ew,
                             float* __restrict__ t9)
{
    __shared__ float sw[CH*9];
    const int tid = threadIdx.x;
    for (int i = tid; i < CH*9; i += 256) sw[i] = ew[i];
    __syncthreads();

    const int warp = tid >> 5, lane = tid & 31;
    const int pix = blockIdx.x * 8 + warp;
    const float4* xp = (const float4*)(x + (size_t)pix*CH) + lane*2;
    float4 v0 = xp[0], v1 = xp[1];
    float xa[8] = {v0.x,v0.y,v0.z,v0.w,v1.x,v1.y,v1.z,v1.w};

    float acc[9] = {};
    #pragma unroll
    for (int i = 0; i < 8; i++) {
        const int c = lane*8 + i;
        #pragma unroll
        for (int k = 0; k < 9; k++) acc[k] += xa[i] * sw[c*9 + k];
    }
    #pragma unroll
    for (int k = 0; k < 9; k++)
        #pragma unroll
        for (int o = 16; o; o >>= 1)
            acc[k] += __shfl_xor_sync(0xffffffffu, acc[k], o);
    if (lane < 9) t9[(size_t)pix*9 + lane] = acc[lane];
}

// ----------------------------------------------------------------------------
// Edge conv stage 2: 9-point stencil + abs
// ----------------------------------------------------------------------------
__global__ void edge_stencil_kernel(const float* __restrict__ t9,
                                    float* __restrict__ edge)
{
    const int pix = blockIdx.x * 256 + threadIdx.x;
    const int b = pix >> 12, y = (pix >> 6) & 63, xx = pix & 63;
    float s = 0.f;
    #pragma unroll
    for (int ky = 0; ky < 3; ky++) {
        const int yy = y + ky - 1;
        if (yy < 0 || yy > 63) continue;
        #pragma unroll
        for (int kx = 0; kx < 3; kx++) {
            const int xw = xx + kx - 1;
            if (xw < 0 || xw > 63) continue;
            s += t9[(size_t)((b*64 + yy)*64 + xw)*9 + ky*3 + kx];
        }
    }
    edge[pix] = fabsf(s);
}

// ----------------------------------------------------------------------------
// 3x3 avgpool + tiny MLP + softmax -> per-pixel scale weights
// ----------------------------------------------------------------------------
__global__ void wts_kernel(const float* __restrict__ edge,
                           const float* __restrict__ w1, const float* __restrict__ b1,
                           const float* __restrict__ w2, const float* __restrict__ b2,
                           float* __restrict__ wts)
{
    int pix = blockIdx.x * blockDim.x + threadIdx.x;
    if (pix >= NTOK) return;
    int b = pix >> 12, y = (pix >> 6) & 63, xx = pix & 63;
    float s = 0.f;
    for (int dy = -1; dy <= 1; dy++) {
        int yy = y + dy; if (yy < 0 || yy > 63) continue;
        for (int dx = -1; dx <= 1; dx++) {
            int xw = xx + dx; if (xw < 0 || xw > 63) continue;
            s += edge[(b*64 + yy)*64 + xw];
        }
    }
    float e = s * (1.f/9.f);
    float lg[3] = {b2[0], b2[1], b2[2]};
    #pragma unroll
    for (int j = 0; j < 16; j++) {
        float h = fmaxf(e * w1[j] + b1[j], 0.f);
        lg[0] += h * w2[j*3 + 0];
        lg[1] += h * w2[j*3 + 1];
        lg[2] += h * w2[j*3 + 2];
    }
    float mx = fmaxf(lg[0], fmaxf(lg[1], lg[2]));
    float e0 = expf(lg[0]-mx), e1 = expf(lg[1]-mx), e2 = expf(lg[2]-mx);
    float inv = 1.f / (e0 + e1 + e2);
    wts[pix*3+0] = e0*inv;
    wts[pix*3+1] = e1*inv;
    wts[pix*3+2] = e2*inv;
}

// ----------------------------------------------------------------------------
// DlightConv
// ----------------------------------------------------------------------------
__global__ void dlight_kernel(const float* __restrict__ S1,
                              const float* __restrict__ dlw,
                              const float* __restrict__ dlb,
                              float* __restrict__ xdl)
{
    __shared__ float part[8][16];
    __shared__ float probs[16];
    const int bx = blockIdx.x;
    const int b = bx >> 8, p1 = (bx >> 4) & 15, p2 = bx & 15;
    const int c = threadIdx.x;

    float vals[16];
    float mean = 0.f;
    #pragma unroll
    for (int wi = 0; wi < 16; wi++) {
        int r = p1*4 + (wi >> 2), cc = p2*4 + (wi & 3);
        vals[wi] = S1[((size_t)((b*64 + r)*64 + cc))*CH + c];
        mean += vals[wi];
    }
    mean *= (1.f/16.f);

    float contrib[16];
    #pragma unroll
    for (int j = 0; j < 16; j++) contrib[j] = mean * dlw[c*16 + j];
    #pragma unroll
    for (int j = 0; j < 16; j++)
        #pragma unroll
        for (int o = 16; o; o >>= 1)
            contrib[j] += __shfl_xor_sync(0xffffffffu, contrib[j], o);
    if ((c & 31) == 0) {
        #pragma unroll
        for (int j = 0; j < 16; j++) part[c >> 5][j] = contrib[j];
    }
    __syncthreads();
    if (c == 0) {
        float lg[16], mx = -1e30f;
        #pragma unroll
        for (int j = 0; j < 16; j++) {
            float v = dlb[j];
            #pragma unroll
            for (int w = 0; w < 8; w++) v += part[w][j];
            lg[j] = v;
            mx = fmaxf(mx, v);
        }
        float sum = 0.f;
        #pragma unroll
        for (int j = 0; j < 16; j++) { lg[j] = expf(lg[j] - mx); sum += lg[j]; }
        float inv = 1.f / sum;
        #pragma unroll
        for (int j = 0; j < 16; j++) probs[j] = lg[j] * inv;
    }
    __syncthreads();
    float acc = 0.f;
    #pragma unroll
    for (int wi = 0; wi < 16; wi++) acc += vals[wi] * probs[wi];
    xdl[(size_t)bx*CH + c] = acc;
}

// ----------------------------------------------------------------------------
// Axial attention
// ----------------------------------------------------------------------------
__global__ void axial_kernel(const float* __restrict__ Q,
                             const float* __restrict__ K,
                             const float* __restrict__ V,
                             const float* __restrict__ gsp,
                             const float* __restrict__ gbp,
                             float* __restrict__ out,
                             int axis)
{
    __shared__ float sQ[16][CH];
    __shared__ float sK[16][CH];
    __shared__ float sc[16][17];
    const int blk = blockIdx.x;
    const int b = blk >> 4, f = blk & 15;
    const int t = threadIdx.x;

    for (int idx = t; idx < 16*CH; idx += 256) {
        int i = idx >> 8, c = idx & 255;
        size_t tok = (axis == 0) ? (size_t)((b*16 + f)*16 + i)
                                 : (size_t)((b*16 + i)*16 + f);
        sQ[i][c] = Q[tok*CH + c];
        sK[i][c] = K[tok*CH + c];
    }
    __syncthreads();

    {
        int w = t >> 4, v = t & 15;
        float dot = 0.f;
        #pragma unroll 8
        for (int c = 0; c < CH; c++) dot += sQ[w][c] * sK[v][c];
        float gs = gsp[0], gb0 = gbp[0];
        float d2 = (float)((v - w) * (v - w));
        sc[w][v] = dot - (gs * d2 + gb0);
    }
    __syncthreads();
    if (t < 16) {
        float mx = -1e30f;
        #pragma unroll
        for (int v = 0; v < 16; v++) mx = fmaxf(mx, sc[t][v]);
        float sum = 0.f;
        #pragma unroll
        for (int v = 0; v < 16; v++) { float e = expf(sc[t][v] - mx); sc[t][v] = e; sum += e; }
        float inv = 1.f / sum;
        #pragma unroll
        for (int v = 0; v < 16; v++) sc[t][v] *= inv;
    }
    __syncthreads();

    const int d = t;
    float acc[16] = {};
    #pragma unroll
    for (int v = 0; v < 16; v++) {
        size_t tokv = (axis == 0) ? (size_t)((b*16 + f)*16 + v)
                                  : (size_t)((b*16 + v)*16 + f);
        float vv = V[tokv*CH + d];
        #pragma unroll
        for (int w = 0; w < 16; w++) acc[w] += sc[w][v] * vv;
    }
    #pragma unroll
    for (int w = 0; w < 16; w++) {
        size_t tokw = (axis == 0) ? (size_t)((b*16 + f)*16 + w)
                                  : (size_t)((b*16 + w)*16 + f);
        if (axis == 0) out[tokw*CH + d] = acc[w];
        else           out[tokw*CH + d] += acc[w];
    }
}

// ----------------------------------------------------------------------------
// Build Z = [upsampled x_g | blended h_map]
// ----------------------------------------------------------------------------
__global__ void zbuild_kernel(const float* __restrict__ xg,
                              const float* __restrict__ S0,
                              const float* __restrict__ S1,
                              const float* __restrict__ S2,
                              const float* __restrict__ wts,
                              float* __restrict__ Z)
{
    const int pix = blockIdx.x;
    const int c = threadIdx.x;
    const int b = pix >> 12, y = (pix >> 6) & 63, xx = pix & 63;
    const float scl = 15.f / 63.f;

    float pr = y * scl;
    int r0 = (int)floorf(pr);
    float tr = pr - (float)r0;
    int r1 = min(r0 + 1, 15);
    float pc = xx * scl;
    int c0 = (int)floorf(pc);
    float tc = pc - (float)c0;
    int c1 = min(c0 + 1, 15);

    size_t base = (size_t)b * 256;
    float v00 = xg[(base + r0*16 + c0)*CH + c];
    float v01 = xg[(base + r0*16 + c1)*CH + c];
    float v10 = xg[(base + r1*16 + c0)*CH + c];
    float v11 = xg[(base + r1*16 + c1)*CH + c];
    float left  = v00*(1.f-tr) + v10*tr;
    float right = v01*(1.f-tr) + v11*tr;
    float interp = left*(1.f-tc) + right*tc;

    size_t zb = (size_t)pix*512;
    Z[zb + c] = interp;

    float w0 = wts[pix*3+0], w1 = wts[pix*3+1], w2 = wts[pix*3+2];
    size_t sb = (size_t)pix*CH + c;
    Z[zb + 256 + c] = w0*S0[sb] + w1*S1[sb] + w2*S2[sb];
}

// ----------------------------------------------------------------------------
// Host launch
// ----------------------------------------------------------------------------
extern "C" void kernel_launch(void* const* d_in, const int* in_sizes, int n_in,
                              void* d_out, int out_size)
{
    const float* x      = (const float*)d_in[0];
    const float* attn_w = (const float*)d_in[1];
    const float* attn_b = (const float*)d_in[2];
    const float* edge_w = (const float*)d_in[3];
    const float* mlp_w1 = (const float*)d_in[4];
    const float* mlp_b1 = (const float*)d_in[5];
    const float* mlp_w2 = (const float*)d_in[6];
    const float* mlp_b2 = (const float*)d_in[7];
    const float* dl_w   = (const float*)d_in[8];
    const float* dl_b   = (const float*)d_in[9];
    const float* ax_w   = (const float*)d_in[10];
    const float* ax_b   = (const float*)d_in[11];
    const float* g_sh   = (const float*)d_in[12];
    const float* g_bi   = (const float*)d_in[13];
    const float* sq_w   = (const float*)d_in[14];
    const float* sq_b   = (const float*)d_in[15];
    float* out = (float*)d_out;

    float *Qb, *Kb, *Vb, *CTXb, *Sb, *T9b, *EDGEb, *WTSb, *XDLb, *AQb, *AKb, *AVb, *XGb, *Zb;
    cudaGetSymbolAddress((void**)&Qb,   g_Q);
    cudaGetSymbolAddress((void**)&Kb,   g_K);
    cudaGetSymbolAddress((void**)&Vb,   g_V);
    cudaGetSymbolAddress((void**)&CTXb, g_CTX);
    cudaGetSymbolAddress((void**)&Sb,   g_S);
    cudaGetSymbolAddress((void**)&T9b,  g_t9);
    cudaGetSymbolAddress((void**)&EDGEb,g_edge);
    cudaGetSymbolAddress((void**)&WTSb, g_wts);
    cudaGetSymbolAddress((void**)&XDLb, g_xdl);
    cudaGetSymbolAddress((void**)&AQb,  g_aQ);
    cudaGetSymbolAddress((void**)&AKb,  g_aK);
    cudaGetSymbolAddress((void**)&AVb,  g_aV);
    cudaGetSymbolAddress((void**)&XGb,  g_xg);
    cudaGetSymbolAddress((void**)&Zb,   g_Z);

    const dim3 gg_big(CH/128, NTOK/128);     // (2, 512)
    const dim3 gg_small(CH/128, NDTOK/128);  // (2, 32)
    const dim3 attn_grid(1024, 4);

    // ---- 3 window-attention branches ----
    for (int br = 0; br < 3; br++) {
        const float* Wq = attn_w + (size_t)(br*4 + 0)*CH*CH;
        const float* Wk = attn_w + (size_t)(br*4 + 1)*CH*CH;
        const float* Wv = attn_w + (size_t)(br*4 + 2)*CH*CH;
        const float* Wo = attn_w + (size_t)(br*4 + 3)*CH*CH;
        const float* bq = attn_b + (br*4 + 0)*CH;
        const float* bk = attn_b + (br*4 + 1)*CH;
        const float* bv = attn_b + (br*4 + 2)*CH;
        const float* bo = attn_b + (br*4 + 3)*CH;

        gemm128<<<gg_big, 256>>>(x, Wq, bq, Qb, NTOK, CH, CH, 0);
        gemm128<<<gg_big, 256>>>(x, Wk, bk, Kb, NTOK, CH, CH, 0);
        gemm128<<<gg_big, 256>>>(x, Wv, bv, Vb, NTOK, CH, CH, 0);

        if (br == 0)      winattn_kernel<2><<<attn_grid, 128>>>((const float4*)Qb, (const float4*)Kb, (const float4*)Vb, (float4*)CTXb);
        else if (br == 1) winattn_kernel<4><<<attn_grid, 128>>>((const float4*)Qb, (const float4*)Kb, (const float4*)Vb, (float4*)CTXb);
        else              winattn_kernel<8><<<attn_grid, 128>>>((const float4*)Qb, (const float4*)Kb, (const float4*)Vb, (float4*)CTXb);

        gemm128<<<gg_big, 256>>>(CTXb, Wo, bo, Sb + (size_t)br*NTOK*CH, NTOK, CH, CH, 0);
    }

    // ---- edge selector (GEMM-ized conv) ----
    conv9_kernel<<<NTOK/8, 256>>>(x, edge_w, T9b);
    edge_stencil_kernel<<<NTOK/256, 256>>>(T9b, EDGEb);
    wts_kernel<<<NTOK/256, 256>>>(EDGEb, mlp_w1, mlp_b1, mlp_w2, mlp_b2, WTSb);

    // ---- DlightConv (reuses ws=4 branch output S[1]) ----
    dlight_kernel<<<NDTOK, 256>>>(Sb + (size_t)1*NTOK*CH, dl_w, dl_b, XDLb);

    // ---- axial projections ----
    gemm128<<<gg_small, 256>>>(XDLb, ax_w + 0*CH*CH, ax_b + 0*CH, AQb, NDTOK, CH, CH, 0);
    gemm128<<<gg_small, 256>>>(XDLb, ax_w + 1*CH*CH, ax_b + 1*CH, AKb, NDTOK, CH, CH, 0);
    gemm128<<<gg_small, 256>>>(XDLb, ax_w + 2*CH*CH, ax_b + 2*CH, AVb, NDTOK, CH, CH, 0);

    // ---- axial attention ----
    axial_kernel<<<BSZ*PP, 256>>>(AQb, AKb, AVb, g_sh, g_bi, XGb, 0);
    axial_kernel<<<BSZ*PP, 256>>>(AQb, AKb, AVb, g_sh, g_bi, XGb, 1);

    // ---- Z build + final projection ----
    zbuild_kernel<<<NTOK, 256>>>(XGb,
                                 Sb + (size_t)0*NTOK*CH,
                                 Sb + (size_t)1*NTOK*CH,
                                 Sb + (size_t)2*NTOK*CH,
                                 WTSb, Zb);

    gemm128<<<gg_big, 256>>>(Zb, sq_w, sq_b, out, NTOK, CH, 2*CH, 1);
}

// round 4
// speedup vs baseline: 3.3476x; 1.3991x over previous
#include <cuda_runtime.h>
#include <cuda_bf16.h>
#include <math.h>
#include <stdint.h>

// ----------------------------------------------------------------------------
// Problem constants
// ----------------------------------------------------------------------------
#define BSZ   16
#define HIMG  64
#define WIMG  64
#define CH    256
#define NTOK  (BSZ*HIMG*WIMG)       // 65536
#define NHEAD 8
#define HS    32
#define PP    16
#define NDTOK (BSZ*PP*PP)           // 4096

// Weight slots (bf16 hi/lo, [N][K] layout)
#define WSLOT_ATTN   0                         // 12 matrices of 256x256
#define WSLOT_AX     (12*65536)                // 3 matrices of 256x256
#define WSLOT_SQ     (12*65536 + 3*65536)      // 1 matrix 256x512
#define WTOTAL       (WSLOT_SQ + 256*512)

// ----------------------------------------------------------------------------
// Scratch
// ----------------------------------------------------------------------------
__device__ float g_Q[NTOK*CH];
__device__ float g_K[NTOK*CH];
__device__ float g_V[NTOK*CH];
__device__ float g_S[3][NTOK*CH];
__device__ __nv_bfloat16 g_CTXh[NTOK*CH];
__device__ __nv_bfloat16 g_CTXl[NTOK*CH];
__device__ __nv_bfloat16 g_xh[NTOK*CH];
__device__ __nv_bfloat16 g_xl[NTOK*CH];
__device__ __nv_bfloat16 g_Zh[(size_t)NTOK*2*CH];
__device__ __nv_bfloat16 g_Zl[(size_t)NTOK*2*CH];
__device__ __nv_bfloat16 g_Wh[WTOTAL];
__device__ __nv_bfloat16 g_Wl[WTOTAL];
__device__ __nv_bfloat16 g_xdlh[NDTOK*CH];
__device__ __nv_bfloat16 g_xdll[NDTOK*CH];
__device__ float g_t9[NTOK*9];
__device__ float g_edge[NTOK];
__device__ float g_wts[NTOK*3];
__device__ float g_aQ[NDTOK*CH];
__device__ float g_aK[NDTOK*CH];
__device__ float g_aV[NDTOK*CH];
__device__ float g_xg[NDTOK*CH];

// ----------------------------------------------------------------------------
// mma.sync / ldmatrix helpers (baseline PTX; no sm_103a-only features)
// ----------------------------------------------------------------------------
__device__ __forceinline__ uint32_t smem_u32(const void* p) {
    uint32_t a;
    asm("{ .reg .u64 t; cvta.to.shared.u64 t, %1; cvt.u32.u64 %0, t; }"
        : "=r"(a) : "l"(p));
    return a;
}
__device__ __forceinline__ void ldsm4(uint32_t* r, uint32_t addr) {
    asm volatile("ldmatrix.sync.aligned.m8n8.x4.shared.b16 {%0,%1,%2,%3}, [%4];"
                 : "=r"(r[0]), "=r"(r[1]), "=r"(r[2]), "=r"(r[3]) : "r"(addr));
}
__device__ __forceinline__ void mma16816(float* d, const uint32_t* a,
                                         uint32_t b0, uint32_t b1) {
    asm volatile("mma.sync.aligned.m16n8k16.row.col.f32.bf16.bf16.f32 "
                 "{%0,%1,%2,%3}, {%4,%5,%6,%7}, {%8,%9}, {%0,%1,%2,%3};"
                 : "+f"(d[0]), "+f"(d[1]), "+f"(d[2]), "+f"(d[3])
                 : "r"(a[0]), "r"(a[1]), "r"(a[2]), "r"(a[3]), "r"(b0), "r"(b1));
}

// ----------------------------------------------------------------------------
// bf16x3 split GEMM via mma.sync:
//   C[M,256] = (Ah+Al)[M,K] @ (Bh+Bl)[256,K]^T + bias   (drop Al*Bl)
// Virtual K-loop over 3 products: p0 Ah*Bh, p1 Ah*Bl, p2 Al*Bh.
// Block 128x128 (grid: x=N/128=2, y=M/128), 8 warps (4M x 2N), warp 32x64.
// k-chunk 32, double-buffered smem, reg prefetch.
// ----------------------------------------------------------------------------
__global__ __launch_bounds__(256)
void gemm_mma(const __nv_bfloat16* __restrict__ Ah, const __nv_bfloat16* __restrict__ Al,
              const __nv_bfloat16* __restrict__ Bh, const __nv_bfloat16* __restrict__ Bl,
              const float* __restrict__ bias, float* __restrict__ Cm, int K)
{
    __shared__ __nv_bfloat16 sA[2][128][40];
    __shared__ __nv_bfloat16 sB[2][128][40];

    const int t = threadIdx.x;
    const int wid = t >> 5, lane = t & 31;
    const int row0 = blockIdx.y * 128;
    const int col0 = blockIdx.x * 128;
    const int mw = wid & 3;        // 0..3  (M)
    const int nw = wid >> 2;       // 0..1  (N)

    const int NCK = K >> 5;
    const int NC3 = NCK * 3;

    const int lrow = t >> 1;              // 0..127
    const int lseg = (t & 1) * 16;        // bf16 offset in row: 0 or 16

    float acc[2][8][4];
    #pragma unroll
    for (int i = 0; i < 2; i++)
        #pragma unroll
        for (int j = 0; j < 8; j++)
            #pragma unroll
            for (int q = 0; q < 4; q++) acc[i][j][q] = 0.f;

    // ---- load chunk 0 ----
    uint4 ra0, ra1, rb0, rb1;
    {
        const uint4* ap = (const uint4*)(Ah + (size_t)(row0 + lrow) * K + lseg);
        ra0 = ap[0]; ra1 = ap[1];
        const uint4* bp = (const uint4*)(Bh + (size_t)(col0 + lrow) * K + lseg);
        rb0 = bp[0]; rb1 = bp[1];
    }
    *(uint4*)&sA[0][lrow][lseg]     = ra0;
    *(uint4*)&sA[0][lrow][lseg + 8] = ra1;
    *(uint4*)&sB[0][lrow][lseg]     = rb0;
    *(uint4*)&sB[0][lrow][lseg + 8] = rb1;
    __syncthreads();

    for (int c = 0; c < NC3; c++) {
        const int buf = c & 1;

        if (c + 1 < NC3) {
            const int cn = c + 1;
            const int p = cn / NCK;
            const int k0 = (cn % NCK) << 5;
            const __nv_bfloat16* Asrc = (p == 2) ? Al : Ah;
            const __nv_bfloat16* Bsrc = (p == 1) ? Bl : Bh;
            const uint4* ap = (const uint4*)(Asrc + (size_t)(row0 + lrow) * K + k0 + lseg);
            ra0 = ap[0]; ra1 = ap[1];
            const uint4* bp = (const uint4*)(Bsrc + (size_t)(col0 + lrow) * K + k0 + lseg);
            rb0 = bp[0]; rb1 = bp[1];
        }

        // ---- compute on buf: 2 k16 steps ----
        #pragma unroll
        for (int ks = 0; ks < 2; ks++) {
            uint32_t af[2][4];
            #pragma unroll
            for (int mt = 0; mt < 2; mt++) {
                uint32_t a = smem_u32(&sA[buf][mw*32 + mt*16 + (lane & 15)]
                                          [ks*16 + ((lane >> 4) << 3)]);
                ldsm4(af[mt], a);
            }
            uint32_t bf[4][4];
            #pragma unroll
            for (int j = 0; j < 4; j++) {
                uint32_t a = smem_u32(&sB[buf][nw*64 + j*16 + (lane & 7) + ((lane >> 4) << 3)]
                                          [ks*16 + (((lane >> 3) & 1) << 3)]);
                ldsm4(bf[j], a);
            }
            #pragma unroll
            for (int mt = 0; mt < 2; mt++)
                #pragma unroll
                for (int j = 0; j < 4; j++) {
                    mma16816(acc[mt][2*j],     af[mt], bf[j][0], bf[j][1]);
                    mma16816(acc[mt][2*j + 1], af[mt], bf[j][2], bf[j][3]);
                }
        }

        if (c + 1 < NC3) {
            const int nb = buf ^ 1;
            __syncthreads();
            *(uint4*)&sA[nb][lrow][lseg]     = ra0;
            *(uint4*)&sA[nb][lrow][lseg + 8] = ra1;
            *(uint4*)&sB[nb][lrow][lseg]     = rb0;
            *(uint4*)&sB[nb][lrow][lseg + 8] = rb1;
            __syncthreads();
        }
    }

    // ---- epilogue: acc + bias -> C ----
    #pragma unroll
    for (int mt = 0; mt < 2; mt++) {
        const int r_ = row0 + mw*32 + mt*16 + (lane >> 2);
        #pragma unroll
        for (int j = 0; j < 8; j++) {
            const int c_ = col0 + nw*64 + j*8 + (lane & 3)*2;
            const float b0 = bias[c_], b1 = bias[c_ + 1];
            float2 v0 = make_float2(acc[mt][j][0] + b0, acc[mt][j][1] + b1);
            float2 v1 = make_float2(acc[mt][j][2] + b0, acc[mt][j][3] + b1);
            *(float2*)&Cm[(size_t)r_ * 256 + c_]       = v0;
            *(float2*)&Cm[(size_t)(r_ + 8) * 256 + c_] = v1;
        }
    }
}

// ----------------------------------------------------------------------------
// Conversions: fp32 -> bf16 hi/lo
// ----------------------------------------------------------------------------
__device__ __forceinline__ void split1(float v, __nv_bfloat16& h, __nv_bfloat16& l) {
    h = __float2bfloat16(v);
    l = __float2bfloat16(v - __bfloat162float(h));
}

__global__ void split4_kernel(const float4* __restrict__ X,
                              __nv_bfloat16* __restrict__ Xh,
                              __nv_bfloat16* __restrict__ Xl)
{
    const size_t i = (size_t)blockIdx.x * 256 + threadIdx.x;
    float4 v = X[i];
    __nv_bfloat16 h0, h1, h2, h3, l0, l1, l2, l3;
    split1(v.x, h0, l0); split1(v.y, h1, l1);
    split1(v.z, h2, l2); split1(v.w, h3, l3);
    __nv_bfloat162 ph0 = __nv_bfloat162(h0, h1), ph1 = __nv_bfloat162(h2, h3);
    __nv_bfloat162 pl0 = __nv_bfloat162(l0, l1), pl1 = __nv_bfloat162(l2, l3);
    uint2 ph, pl;
    ph.x = *(uint32_t*)&ph0; ph.y = *(uint32_t*)&ph1;
    pl.x = *(uint32_t*)&pl0; pl.y = *(uint32_t*)&pl1;
    *(uint2*)(Xh + i * 4) = ph;
    *(uint2*)(Xl + i * 4) = pl;
}

// weights (K=256,N=256) -> transposed [N][K] hi/lo (batched over matrices)
__global__ void convw_t_kernel(const float* __restrict__ W,
                               __nv_bfloat16* __restrict__ Wh,
                               __nv_bfloat16* __restrict__ Wl)
{
    const int idx = blockIdx.x * 256 + threadIdx.x;
    const int m = idx >> 16, r = idx & 65535;
    const int k = r >> 8, n = r & 255;
    float w = W[idx];
    __nv_bfloat16 h, l; split1(w, h, l);
    const size_t o = ((size_t)m << 16) + (n << 8) + k;
    Wh[o] = h; Wl[o] = l;
}

// direct convert (already [N][K])
__global__ void convw_kernel(const float* __restrict__ W,
                             __nv_bfloat16* __restrict__ Wh,
                             __nv_bfloat16* __restrict__ Wl)
{
    const int idx = blockIdx.x * 256 + threadIdx.x;
    __nv_bfloat16 h, l; split1(W[idx], h, l);
    Wh[idx] = h; Wl[idx] = l;
}

// ----------------------------------------------------------------------------
// Window attention (fp32 in, bf16 hi/lo ctx out)
// ----------------------------------------------------------------------------
template<int WS>
__global__ __launch_bounds__(128)
void winattn_kernel(const float4* __restrict__ Q4,
                    const float4* __restrict__ K4,
                    const float4* __restrict__ V4,
                    __nv_bfloat16* __restrict__ CTXh,
                    __nv_bfloat16* __restrict__ CTXl)
{
    constexpr int WIN = WS*WS;
    constexpr int G   = 64 / WIN;
    constexpr int NW  = HIMG / WS;
    __shared__ float4 sK[2][64][9];
    __shared__ float4 sV[2][64][9];

    const int t    = threadIdx.x;
    const int slot = t >> 6;
    const int tt   = t & 63;
    const int head = blockIdx.y * 2 + slot;
    const int g    = tt / WIN;
    const int qi   = tt % WIN;
    const int widx = blockIdx.x * G + g;
    const int b    = widx / (NW*NW);
    const int rem  = widx % (NW*NW);
    const int p1   = rem / NW, p2 = rem % NW;
    const int r    = p1*WS + qi/WS;
    const int cc   = p2*WS + qi%WS;
    const int token = (b*HIMG + r)*WIMG + cc;
    const size_t base4 = (size_t)token*(CH/4) + head*(HS/4);

    float4 q[8];
    #pragma unroll
    for (int d = 0; d < 8; d++) {
        q[d]            = Q4[base4 + d];
        sK[slot][tt][d] = K4[base4 + d];
        sV[slot][tt][d] = V4[base4 + d];
    }
    __syncthreads();

    const float scale = 0.17677669529663687f;
    float sc[WIN];
    float mx = -1e30f;
    #pragma unroll
    for (int v = 0; v < WIN; v++) {
        float dot = 0.f;
        #pragma unroll
        for (int d = 0; d < 8; d++) {
            float4 k4 = sK[slot][g*WIN + v][d];
            dot += q[d].x*k4.x + q[d].y*k4.y + q[d].z*k4.z + q[d].w*k4.w;
        }
        dot *= scale;
        sc[v] = dot;
        mx = fmaxf(mx, dot);
    }
    float sum = 0.f;
    #pragma unroll
    for (int v = 0; v < WIN; v++) { sc[v] = expf(sc[v] - mx); sum += sc[v]; }
    const float inv = 1.f / sum;
    #pragma unroll
    for (int v = 0; v < WIN; v++) sc[v] *= inv;

    const size_t basee = base4 * 4;
    #pragma unroll
    for (int d = 0; d < 8; d++) {
        float4 a = make_float4(0.f, 0.f, 0.f, 0.f);
        #pragma unroll
        for (int v = 0; v < WIN; v++) {
            float4 vv = sV[slot][g*WIN + v][d];
            a.x += sc[v]*vv.x; a.y += sc[v]*vv.y;
            a.z += sc[v]*vv.z; a.w += sc[v]*vv.w;
        }
        __nv_bfloat16 h0,h1,h2,h3,l0,l1,l2,l3;
        split1(a.x,h0,l0); split1(a.y,h1,l1); split1(a.z,h2,l2); split1(a.w,h3,l3);
        __nv_bfloat162 ph0 = __nv_bfloat162(h0,h1), ph1 = __nv_bfloat162(h2,h3);
        __nv_bfloat162 pl0 = __nv_bfloat162(l0,l1), pl1 = __nv_bfloat162(l2,l3);
        uint2 ph, pl;
        ph.x = *(uint32_t*)&ph0; ph.y = *(uint32_t*)&ph1;
        pl.x = *(uint32_t*)&pl0; pl.y = *(uint32_t*)&pl1;
        *(uint2*)(CTXh + basee + d*4) = ph;
        *(uint2*)(CTXl + basee + d*4) = pl;
    }
}

// ----------------------------------------------------------------------------
// Edge conv stage 1: t9[pix,k] = sum_c x[pix,c] * w[c,k]
// ----------------------------------------------------------------------------
__global__ void conv9_kernel(const float* __restrict__ x,
                             const float* __restrict__ ew,
                             float* __restrict__ t9)
{
    __shared__ float sw[CH*9];
    const int tid = threadIdx.x;
    for (int i = tid; i < CH*9; i += 256) sw[i] = ew[i];
    __syncthreads();

    const int warp = tid >> 5, lane = tid & 31;
    const int pix = blockIdx.x * 8 + warp;
    const float4* xp = (const float4*)(x + (size_t)pix*CH) + lane*2;
    float4 v0 = xp[0], v1 = xp[1];
    float xa[8] = {v0.x,v0.y,v0.z,v0.w,v1.x,v1.y,v1.z,v1.w};

    float acc[9] = {};
    #pragma unroll
    for (int i = 0; i < 8; i++) {
        const int c = lane*8 + i;
        #pragma unroll
        for (int k = 0; k < 9; k++) acc[k] += xa[i] * sw[c*9 + k];
    }
    #pragma unroll
    for (int k = 0; k < 9; k++)
        #pragma unroll
        for (int o = 16; o; o >>= 1)
            acc[k] += __shfl_xor_sync(0xffffffffu, acc[k], o);
    if (lane < 9) t9[(size_t)pix*9 + lane] = acc[lane];
}

__global__ void edge_stencil_kernel(const float* __restrict__ t9,
                                    float* __restrict__ edge)
{
    const int pix = blockIdx.x * 256 + threadIdx.x;
    const int b = pix >> 12, y = (pix >> 6) & 63, xx = pix & 63;
    float s = 0.f;
    #pragma unroll
    for (int ky = 0; ky < 3; ky++) {
        const int yy = y + ky - 1;
        if (yy < 0 || yy > 63) continue;
        #pragma unroll
        for (int kx = 0; kx < 3; kx++) {
            const int xw = xx + kx - 1;
            if (xw < 0 || xw > 63) continue;
            s += t9[(size_t)((b*64 + yy)*64 + xw)*9 + ky*3 + kx];
        }
    }
    edge[pix] = fabsf(s);
}

__global__ void wts_kernel(const float* __restrict__ edge,
                           const float* __restrict__ w1, const float* __restrict__ b1,
                           const float* __restrict__ w2, const float* __restrict__ b2,
                           float* __restrict__ wts)
{
    int pix = blockIdx.x * blockDim.x + threadIdx.x;
    if (pix >= NTOK) return;
    int b = pix >> 12, y = (pix >> 6) & 63, xx = pix & 63;
    float s = 0.f;
    for (int dy = -1; dy <= 1; dy++) {
        int yy = y + dy; if (yy < 0 || yy > 63) continue;
        for (int dx = -1; dx <= 1; dx++) {
            int xw = xx + dx; if (xw < 0 || xw > 63) continue;
            s += edge[(b*64 + yy)*64 + xw];
        }
    }
    float e = s * (1.f/9.f);
    float lg[3] = {b2[0], b2[1], b2[2]};
    #pragma unroll
    for (int j = 0; j < 16; j++) {
        float h = fmaxf(e * w1[j] + b1[j], 0.f);
        lg[0] += h * w2[j*3 + 0];
        lg[1] += h * w2[j*3 + 1];
        lg[2] += h * w2[j*3 + 2];
    }
    float mx = fmaxf(lg[0], fmaxf(lg[1], lg[2]));
    float e0 = expf(lg[0]-mx), e1 = expf(lg[1]-mx), e2 = expf(lg[2]-mx);
    float inv = 1.f / (e0 + e1 + e2);
    wts[pix*3+0] = e0*inv;
    wts[pix*3+1] = e1*inv;
    wts[pix*3+2] = e2*inv;
}

// ----------------------------------------------------------------------------
// DlightConv (fp32 in, bf16 hi/lo out)
// ----------------------------------------------------------------------------
__global__ void dlight_kernel(const float* __restrict__ S1,
                              const float* __restrict__ dlw,
                              const float* __restrict__ dlb,
                              __nv_bfloat16* __restrict__ xdlh,
                              __nv_bfloat16* __restrict__ xdll)
{
    __shared__ float part[8][16];
    __shared__ float probs[16];
    const int bx = blockIdx.x;
    const int b = bx >> 8, p1 = (bx >> 4) & 15, p2 = bx & 15;
    const int c = threadIdx.x;

    float vals[16];
    float mean = 0.f;
    #pragma unroll
    for (int wi = 0; wi < 16; wi++) {
        int r = p1*4 + (wi >> 2), cc = p2*4 + (wi & 3);
        vals[wi] = S1[((size_t)((b*64 + r)*64 + cc))*CH + c];
        mean += vals[wi];
    }
    mean *= (1.f/16.f);

    float contrib[16];
    #pragma unroll
    for (int j = 0; j < 16; j++) contrib[j] = mean * dlw[c*16 + j];
    #pragma unroll
    for (int j = 0; j < 16; j++)
        #pragma unroll
        for (int o = 16; o; o >>= 1)
            contrib[j] += __shfl_xor_sync(0xffffffffu, contrib[j], o);
    if ((c & 31) == 0) {
        #pragma unroll
        for (int j = 0; j < 16; j++) part[c >> 5][j] = contrib[j];
    }
    __syncthreads();
    if (c == 0) {
        float lg[16], mx = -1e30f;
        #pragma unroll
        for (int j = 0; j < 16; j++) {
            float v = dlb[j];
            #pragma unroll
            for (int w = 0; w < 8; w++) v += part[w][j];
            lg[j] = v;
            mx = fmaxf(mx, v);
        }
        float sum = 0.f;
        #pragma unroll
        for (int j = 0; j < 16; j++) { lg[j] = expf(lg[j] - mx); sum += lg[j]; }
        float inv = 1.f / sum;
        #pragma unroll
        for (int j = 0; j < 16; j++) probs[j] = lg[j] * inv;
    }
    __syncthreads();
    float acc = 0.f;
    #pragma unroll
    for (int wi = 0; wi < 16; wi++) acc += vals[wi] * probs[wi];
    __nv_bfloat16 h, l; split1(acc, h, l);
    xdlh[(size_t)bx*CH + c] = h;
    xdll[(size_t)bx*CH + c] = l;
}

// ----------------------------------------------------------------------------
// Axial attention (fp32)
// ----------------------------------------------------------------------------
__global__ void axial_kernel(const float* __restrict__ Q,
                             const float* __restrict__ K,
                             const float* __restrict__ V,
                             const float* __restrict__ gsp,
                             const float* __restrict__ gbp,
                             float* __restrict__ out,
                             int axis)
{
    __shared__ float sQ[16][CH];
    __shared__ float sK[16][CH];
    __shared__ float sc[16][17];
    const int blk = blockIdx.x;
    const int b = blk >> 4, f = blk & 15;
    const int t = threadIdx.x;

    for (int idx = t; idx < 16*CH; idx += 256) {
        int i = idx >> 8, c = idx & 255;
        size_t tok = (axis == 0) ? (size_t)((b*16 + f)*16 + i)
                                 : (size_t)((b*16 + i)*16 + f);
        sQ[i][c] = Q[tok*CH + c];
        sK[i][c] = K[tok*CH + c];
    }
    __syncthreads();

    {
        int w = t >> 4, v = t & 15;
        float dot = 0.f;
        #pragma unroll 8
        for (int c = 0; c < CH; c++) dot += sQ[w][c] * sK[v][c];
        float gs = gsp[0], gb0 = gbp[0];
        float d2 = (float)((v - w) * (v - w));
        sc[w][v] = dot - (gs * d2 + gb0);
    }
    __syncthreads();
    if (t < 16) {
        float mx = -1e30f;
        #pragma unroll
        for (int v = 0; v < 16; v++) mx = fmaxf(mx, sc[t][v]);
        float sum = 0.f;
        #pragma unroll
        for (int v = 0; v < 16; v++) { float e = expf(sc[t][v] - mx); sc[t][v] = e; sum += e; }
        float inv = 1.f / sum;
        #pragma unroll
        for (int v = 0; v < 16; v++) sc[t][v] *= inv;
    }
    __syncthreads();

    const int d = t;
    float acc[16] = {};
    #pragma unroll
    for (int v = 0; v < 16; v++) {
        size_t tokv = (axis == 0) ? (size_t)((b*16 + f)*16 + v)
                                  : (size_t)((b*16 + v)*16 + f);
        float vv = V[tokv*CH + d];
        #pragma unroll
        for (int w = 0; w < 16; w++) acc[w] += sc[w][v] * vv;
    }
    #pragma unroll
    for (int w = 0; w < 16; w++) {
        size_t tokw = (axis == 0) ? (size_t)((b*16 + f)*16 + w)
                                  : (size_t)((b*16 + w)*16 + f);
        if (axis == 0) out[tokw*CH + d] = acc[w];
        else           out[tokw*CH + d] += acc[w];
    }
}

// ----------------------------------------------------------------------------
// Build Z = [upsampled x_g | blended h_map], bf16 hi/lo out
// ----------------------------------------------------------------------------
__global__ void zbuild_kernel(const float* __restrict__ xg,
                              const float* __restrict__ S0,
                              const float* __restrict__ S1,
                              const float* __restrict__ S2,
                              const float* __restrict__ wts,
                              __nv_bfloat16* __restrict__ Zh,
                              __nv_bfloat16* __restrict__ Zl)
{
    const int pix = blockIdx.x;
    const int c = threadIdx.x;
    const int b = pix >> 12, y = (pix >> 6) & 63, xx = pix & 63;
    const float scl = 15.f / 63.f;

    float pr = y * scl;
    int r0 = (int)floorf(pr);
    float tr = pr - (float)r0;
    int r1 = min(r0 + 1, 15);
    float pc = xx * scl;
    int c0 = (int)floorf(pc);
    float tc = pc - (float)c0;
    int c1 = min(c0 + 1, 15);

    size_t base = (size_t)b * 256;
    float v00 = xg[(base + r0*16 + c0)*CH + c];
    float v01 = xg[(base + r0*16 + c1)*CH + c];
    float v10 = xg[(base + r1*16 + c0)*CH + c];
    float v11 = xg[(base + r1*16 + c1)*CH + c];
    float left  = v00*(1.f-tr) + v10*tr;
    float right = v01*(1.f-tr) + v11*tr;
    float interp = left*(1.f-tc) + right*tc;

    size_t zb = (size_t)pix*512;
    __nv_bfloat16 h, l;
    split1(interp, h, l);
    Zh[zb + c] = h; Zl[zb + c] = l;

    float w0 = wts[pix*3+0], w1 = wts[pix*3+1], w2 = wts[pix*3+2];
    size_t sb = (size_t)pix*CH + c;
    float blend = w0*S0[sb] + w1*S1[sb] + w2*S2[sb];
    split1(blend, h, l);
    Zh[zb + 256 + c] = h; Zl[zb + 256 + c] = l;
}

// ----------------------------------------------------------------------------
// Host launch
// ----------------------------------------------------------------------------
extern "C" void kernel_launch(void* const* d_in, const int* in_sizes, int n_in,
                              void* d_out, int out_size)
{
    const float* x      = (const float*)d_in[0];
    const float* attn_w = (const float*)d_in[1];
    const float* attn_b = (const float*)d_in[2];
    const float* edge_w = (const float*)d_in[3];
    const float* mlp_w1 = (const float*)d_in[4];
    const float* mlp_b1 = (const float*)d_in[5];
    const float* mlp_w2 = (const float*)d_in[6];
    const float* mlp_b2 = (const float*)d_in[7];
    const float* dl_w   = (const float*)d_in[8];
    const float* dl_b   = (const float*)d_in[9];
    const float* ax_w   = (const float*)d_in[10];
    const float* ax_b   = (const float*)d_in[11];
    const float* g_sh   = (const float*)d_in[12];
    const float* g_bi   = (const float*)d_in[13];
    const float* sq_w   = (const float*)d_in[14];
    const float* sq_b   = (const float*)d_in[15];
    float* out = (float*)d_out;

    float *Qb, *Kb, *Vb, *Sb, *T9b, *EDGEb, *WTSb, *AQb, *AKb, *AVb, *XGb;
    __nv_bfloat16 *CTXh, *CTXl, *Xh, *Xl, *Zh, *Zl, *Wh, *Wl, *XDLh, *XDLl;
    cudaGetSymbolAddress((void**)&Qb,   g_Q);
    cudaGetSymbolAddress((void**)&Kb,   g_K);
    cudaGetSymbolAddress((void**)&Vb,   g_V);
    cudaGetSymbolAddress((void**)&Sb,   g_S);
    cudaGetSymbolAddress((void**)&T9b,  g_t9);
    cudaGetSymbolAddress((void**)&EDGEb,g_edge);
    cudaGetSymbolAddress((void**)&WTSb, g_wts);
    cudaGetSymbolAddress((void**)&AQb,  g_aQ);
    cudaGetSymbolAddress((void**)&AKb,  g_aK);
    cudaGetSymbolAddress((void**)&AVb,  g_aV);
    cudaGetSymbolAddress((void**)&XGb,  g_xg);
    cudaGetSymbolAddress((void**)&CTXh, g_CTXh);
    cudaGetSymbolAddress((void**)&CTXl, g_CTXl);
    cudaGetSymbolAddress((void**)&Xh,   g_xh);
    cudaGetSymbolAddress((void**)&Xl,   g_xl);
    cudaGetSymbolAddress((void**)&Zh,   g_Zh);
    cudaGetSymbolAddress((void**)&Zl,   g_Zl);
    cudaGetSymbolAddress((void**)&Wh,   g_Wh);
    cudaGetSymbolAddress((void**)&Wl,   g_Wl);
    cudaGetSymbolAddress((void**)&XDLh, g_xdlh);
    cudaGetSymbolAddress((void**)&XDLl, g_xdll);

    // ---- weight + activation conversions ----
    convw_t_kernel<<<12*65536/256, 256>>>(attn_w, Wh + WSLOT_ATTN, Wl + WSLOT_ATTN);
    convw_t_kernel<<<3*65536/256, 256>>>(ax_w, Wh + WSLOT_AX, Wl + WSLOT_AX);
    convw_kernel<<<256*512/256, 256>>>(sq_w, Wh + WSLOT_SQ, Wl + WSLOT_SQ);
    split4_kernel<<<NTOK*CH/4/256, 256>>>((const float4*)x, Xh, Xl);

    const dim3 gg_big(2, NTOK/128);      // (2, 512)
    const dim3 gg_small(2, NDTOK/128);   // (2, 32)
    const dim3 attn_grid(1024, 4);

    // ---- 3 window-attention branches ----
    for (int br = 0; br < 3; br++) {
        const __nv_bfloat16* Wq_h = Wh + WSLOT_ATTN + (size_t)(br*4 + 0)*65536;
        const __nv_bfloat16* Wq_l = Wl + WSLOT_ATTN + (size_t)(br*4 + 0)*65536;
        const __nv_bfloat16* Wk_h = Wh + WSLOT_ATTN + (size_t)(br*4 + 1)*65536;
        const __nv_bfloat16* Wk_l = Wl + WSLOT_ATTN + (size_t)(br*4 + 1)*65536;
        const __nv_bfloat16* Wv_h = Wh + WSLOT_ATTN + (size_t)(br*4 + 2)*65536;
        const __nv_bfloat16* Wv_l = Wl + WSLOT_ATTN + (size_t)(br*4 + 2)*65536;
        const __nv_bfloat16* Wo_h = Wh + WSLOT_ATTN + (size_t)(br*4 + 3)*65536;
        const __nv_bfloat16* Wo_l = Wl + WSLOT_ATTN + (size_t)(br*4 + 3)*65536;
        const float* bq = attn_b + (br*4 + 0)*CH;
        const float* bk = attn_b + (br*4 + 1)*CH;
        const float* bv = attn_b + (br*4 + 2)*CH;
        const float* bo = attn_b + (br*4 + 3)*CH;

        gemm_mma<<<gg_big, 256>>>(Xh, Xl, Wq_h, Wq_l, bq, Qb, 256);
        gemm_mma<<<gg_big, 256>>>(Xh, Xl, Wk_h, Wk_l, bk, Kb, 256);
        gemm_mma<<<gg_big, 256>>>(Xh, Xl, Wv_h, Wv_l, bv, Vb, 256);

        if (br == 0)      winattn_kernel<2><<<attn_grid, 128>>>((const float4*)Qb, (const float4*)Kb, (const float4*)Vb, CTXh, CTXl);
        else if (br == 1) winattn_kernel<4><<<attn_grid, 128>>>((const float4*)Qb, (const float4*)Kb, (const float4*)Vb, CTXh, CTXl);
        else              winattn_kernel<8><<<attn_grid, 128>>>((const float4*)Qb, (const float4*)Kb, (const float4*)Vb, CTXh, CTXl);

        gemm_mma<<<gg_big, 256>>>(CTXh, CTXl, Wo_h, Wo_l, bo,
                                  Sb + (size_t)br*NTOK*CH, 256);
    }

    // ---- edge selector ----
    conv9_kernel<<<NTOK/8, 256>>>(x, edge_w, T9b);
    edge_stencil_kernel<<<NTOK/256, 256>>>(T9b, EDGEb);
    wts_kernel<<<NTOK/256, 256>>>(EDGEb, mlp_w1, mlp_b1, mlp_w2, mlp_b2, WTSb);

    // ---- DlightConv ----
    dlight_kernel<<<NDTOK, 256>>>(Sb + (size_t)1*NTOK*CH, dl_w, dl_b, XDLh, XDLl);

    // ---- axial projections ----
    gemm_mma<<<gg_small, 256>>>(XDLh, XDLl, Wh + WSLOT_AX + 0*65536, Wl + WSLOT_AX + 0*65536, ax_b + 0*CH, AQb, 256);
    gemm_mma<<<gg_small, 256>>>(XDLh, XDLl, Wh + WSLOT_AX + 1*65536, Wl + WSLOT_AX + 1*65536, ax_b + 1*CH, AKb, 256);
    gemm_mma<<<gg_small, 256>>>(XDLh, XDLl, Wh + WSLOT_AX + 2*65536, Wl + WSLOT_AX + 2*65536, ax_b + 2*CH, AVb, 256);

    // ---- axial attention ----
    axial_kernel<<<BSZ*PP, 256>>>(AQb, AKb, AVb, g_sh, g_bi, XGb, 0);
    axial_kernel<<<BSZ*PP, 256>>>(AQb, AKb, AVb, g_sh, g_bi, XGb, 1);

    // ---- Z build + final projection ----
    zbuild_kernel<<<NTOK, 256>>>(XGb,
                                 Sb + (size_t)0*NTOK*CH,
                                 Sb + (size_t)1*NTOK*CH,
                                 Sb + (size_t)2*NTOK*CH,
                                 WTSb, Zh, Zl);

    gemm_mma<<<gg_big, 256>>>(Zh, Zl, Wh + WSLOT_SQ, Wl + WSLOT_SQ, sq_b, out, 512);
}

// round 5
// speedup vs baseline: 3.9337x; 1.1751x over previous
#include <cuda_runtime.h>
#include <cuda_bf16.h>
#include <math.h>
#include <stdint.h>

// ----------------------------------------------------------------------------
// Problem constants
// ----------------------------------------------------------------------------
#define BSZ   16
#define HIMG  64
#define WIMG  64
#define CH    256
#define NTOK  (BSZ*HIMG*WIMG)       // 65536
#define NHEAD 8
#define HS    32
#define PP    16
#define NDTOK (BSZ*PP*PP)           // 4096

// Weight slots (bf16 hi/lo, [N][K] layout)
#define WSLOT_ATTN   0                         // 12 matrices of 256x256
#define WSLOT_AX     (12*65536)                // 3 matrices of 256x256
#define WSLOT_SQ     (12*65536 + 3*65536)      // 1 matrix 256x512
#define WTOTAL       (WSLOT_SQ + 256*512)

// ----------------------------------------------------------------------------
// Scratch
// ----------------------------------------------------------------------------
__device__ float g_Q[NTOK*CH];
__device__ float g_K[NTOK*CH];
__device__ float g_V[NTOK*CH];
__device__ float g_S[3][NTOK*CH];
__device__ __nv_bfloat16 g_CTXh[NTOK*CH];
__device__ __nv_bfloat16 g_CTXl[NTOK*CH];
__device__ __nv_bfloat16 g_xh[NTOK*CH];
__device__ __nv_bfloat16 g_xl[NTOK*CH];
__device__ __nv_bfloat16 g_Zh[(size_t)NTOK*2*CH];
__device__ __nv_bfloat16 g_Zl[(size_t)NTOK*2*CH];
__device__ __nv_bfloat16 g_Wh[WTOTAL];
__device__ __nv_bfloat16 g_Wl[WTOTAL];
__device__ __nv_bfloat16 g_xdlh[NDTOK*CH];
__device__ __nv_bfloat16 g_xdll[NDTOK*CH];
__device__ float g_t9[NTOK*9];
__device__ float g_edge[NTOK];
__device__ float g_wts[NTOK*3];
__device__ float g_aQ[NDTOK*CH];
__device__ float g_aK[NDTOK*CH];
__device__ float g_aV[NDTOK*CH];
__device__ float g_xg[NDTOK*CH];

// ----------------------------------------------------------------------------
// PTX helpers (baseline sm_80-class PTX only)
// ----------------------------------------------------------------------------
__device__ __forceinline__ uint32_t smem_u32(const void* p) {
    uint32_t a;
    asm("{ .reg .u64 t; cvta.to.shared.u64 t, %1; cvt.u32.u64 %0, t; }"
        : "=r"(a) : "l"(p));
    return a;
}
__device__ __forceinline__ void ldsm4(uint32_t* r, uint32_t addr) {
    asm volatile("ldmatrix.sync.aligned.m8n8.x4.shared.b16 {%0,%1,%2,%3}, [%4];"
                 : "=r"(r[0]), "=r"(r[1]), "=r"(r[2]), "=r"(r[3]) : "r"(addr));
}
__device__ __forceinline__ void mma16816(float* d, const uint32_t* a,
                                         uint32_t b0, uint32_t b1) {
    asm volatile("mma.sync.aligned.m16n8k16.row.col.f32.bf16.bf16.f32 "
                 "{%0,%1,%2,%3}, {%4,%5,%6,%7}, {%8,%9}, {%0,%1,%2,%3};"
                 : "+f"(d[0]), "+f"(d[1]), "+f"(d[2]), "+f"(d[3])
                 : "r"(a[0]), "r"(a[1]), "r"(a[2]), "r"(a[3]), "r"(b0), "r"(b1));
}
#define CP16(dst, src) \
    asm volatile("cp.async.cg.shared.global [%0], [%1], 16;" :: "r"(dst), "l"(src))
#define CP_COMMIT() asm volatile("cp.async.commit_group;" ::: "memory")
#define CP_WAIT1()  asm volatile("cp.async.wait_group 1;" ::: "memory")
#define CP_WAIT0()  asm volatile("cp.async.wait_group 0;" ::: "memory")

// ----------------------------------------------------------------------------
// bf16x3 split GEMM, multi-output tiles, cp.async pipeline:
//   out[m][M,256] = (Ah+Al)[M,K] @ (Bh+Bl)[256,K]^T + bias  (drop Al*Bl)
// k-chunk 32, hi/lo co-resident in smem, double buffered.
// grid.x = 2*nmat (tile = t[blockIdx.x>>1], col half = blockIdx.x&1).
// Block 128 rows x 128 cols, 8 warps (4M x 2N), warp 32x64.
// ----------------------------------------------------------------------------
struct Tile {
    const __nv_bfloat16 *ah, *al, *bh, *bl;
    const float* bias;
    float* out;
};
struct Tiles { Tile t[3]; };

// smem buffer layout (bytes): each matrix chunk is [128][40] bf16 = 10240 B
#define SM_AH  0
#define SM_AL  10240
#define SM_BH  20480
#define SM_BL  30720
#define SM_BUF 40960
#define GEMM_SMEM (2*SM_BUF)

__device__ __forceinline__ void load_chunk(
    uint32_t sbase, const Tile& e, int K, int row0, int col0, int k0, int t)
{
    const int lrow = t >> 1;
    const int lseg = (t & 1) * 16;
    const uint32_t doff = (uint32_t)(lrow * 80 + lseg * 2);
    {
        const __nv_bfloat16* s = e.ah + (size_t)(row0 + lrow) * K + k0 + lseg;
        CP16(sbase + SM_AH + doff,      s);
        CP16(sbase + SM_AH + doff + 16, s + 8);
        s = e.al + (size_t)(row0 + lrow) * K + k0 + lseg;
        CP16(sbase + SM_AL + doff,      s);
        CP16(sbase + SM_AL + doff + 16, s + 8);
    }
    {
        const __nv_bfloat16* s = e.bh + (size_t)(col0 + lrow) * K + k0 + lseg;
        CP16(sbase + SM_BH + doff,      s);
        CP16(sbase + SM_BH + doff + 16, s + 8);
        s = e.bl + (size_t)(col0 + lrow) * K + k0 + lseg;
        CP16(sbase + SM_BL + doff,      s);
        CP16(sbase + SM_BL + doff + 16, s + 8);
    }
}

__global__ __launch_bounds__(256)
void gemm_mma2(Tiles T, int K)
{
    extern __shared__ char sm[];
    const uint32_t sb0 = smem_u32(sm);

    const int t = threadIdx.x;
    const int wid = t >> 5, lane = t & 31;
    const Tile e = T.t[blockIdx.x >> 1];
    const int col0 = (blockIdx.x & 1) * 128;
    const int row0 = blockIdx.y * 128;
    const int mw = wid & 3;        // 0..3  (M)
    const int nw = wid >> 2;       // 0..1  (N)
    const int NC = K >> 5;

    float acc[2][8][4];
    #pragma unroll
    for (int i = 0; i < 2; i++)
        #pragma unroll
        for (int j = 0; j < 8; j++)
            #pragma unroll
            for (int q = 0; q < 4; q++) acc[i][j][q] = 0.f;

    load_chunk(sb0, e, K, row0, col0, 0, t);
    CP_COMMIT();

    // precomputed ldmatrix byte offsets (within a matrix chunk)
    const uint32_t a_off[2] = {
        (uint32_t)((mw*32 + 0*16 + (lane & 15)) * 80),
        (uint32_t)((mw*32 + 1*16 + (lane & 15)) * 80)
    };
    const uint32_t a_col = (uint32_t)(((lane >> 4) << 3) * 2);
    uint32_t b_off[4];
    #pragma unroll
    for (int j = 0; j < 4; j++)
        b_off[j] = (uint32_t)((nw*64 + j*16 + (lane & 7) + ((lane >> 4) << 3)) * 80);
    const uint32_t b_col = (uint32_t)((((lane >> 3) & 1) << 3) * 2);

    for (int c = 0; c < NC; c++) {
        const uint32_t bb = sb0 + (uint32_t)(c & 1) * SM_BUF;

        if (c + 1 < NC) {
            load_chunk(sb0 + (uint32_t)((c + 1) & 1) * SM_BUF, e, K, row0, col0,
                       (c + 1) << 5, t);
            CP_COMMIT();
            CP_WAIT1();
        } else {
            CP_WAIT0();
        }
        __syncthreads();

        #pragma unroll
        for (int ks = 0; ks < 2; ks++) {
            const uint32_t kc = (uint32_t)(ks * 32);   // 16 bf16 = 32 bytes
            uint32_t afh[2][4], afl[2][4], bfh[4][4], bfl[4][4];
            #pragma unroll
            for (int mt = 0; mt < 2; mt++) {
                ldsm4(afh[mt], bb + SM_AH + a_off[mt] + kc + a_col);
                ldsm4(afl[mt], bb + SM_AL + a_off[mt] + kc + a_col);
            }
            #pragma unroll
            for (int j = 0; j < 4; j++) {
                ldsm4(bfh[j], bb + SM_BH + b_off[j] + kc + b_col);
                ldsm4(bfl[j], bb + SM_BL + b_off[j] + kc + b_col);
            }
            #pragma unroll
            for (int mt = 0; mt < 2; mt++)
                #pragma unroll
                for (int j = 0; j < 4; j++) {
                    mma16816(acc[mt][2*j],     afh[mt], bfh[j][0], bfh[j][1]);
                    mma16816(acc[mt][2*j + 1], afh[mt], bfh[j][2], bfh[j][3]);
                    mma16816(acc[mt][2*j],     afh[mt], bfl[j][0], bfl[j][1]);
                    mma16816(acc[mt][2*j + 1], afh[mt], bfl[j][2], bfl[j][3]);
                    mma16816(acc[mt][2*j],     afl[mt], bfh[j][0], bfh[j][1]);
                    mma16816(acc[mt][2*j + 1], afl[mt], bfh[j][2], bfh[j][3]);
                }
        }
        __syncthreads();
    }

    // ---- epilogue: acc + bias -> out ----
    #pragma unroll
    for (int mt = 0; mt < 2; mt++) {
        const int r_ = row0 + mw*32 + mt*16 + (lane >> 2);
        #pragma unroll
        for (int j = 0; j < 8; j++) {
            const int c_ = col0 + nw*64 + j*8 + (lane & 3)*2;
            const float b0 = e.bias[c_], b1 = e.bias[c_ + 1];
            float2 v0 = make_float2(acc[mt][j][0] + b0, acc[mt][j][1] + b1);
            float2 v1 = make_float2(acc[mt][j][2] + b0, acc[mt][j][3] + b1);
            *(float2*)&e.out[(size_t)r_ * 256 + c_]       = v0;
            *(float2*)&e.out[(size_t)(r_ + 8) * 256 + c_] = v1;
        }
    }
}

// ----------------------------------------------------------------------------
// Conversions: fp32 -> bf16 hi/lo
// ----------------------------------------------------------------------------
__device__ __forceinline__ void split1(float v, __nv_bfloat16& h, __nv_bfloat16& l) {
    h = __float2bfloat16(v);
    l = __float2bfloat16(v - __bfloat162float(h));
}

__global__ void split4_kernel(const float4* __restrict__ X,
                              __nv_bfloat16* __restrict__ Xh,
                              __nv_bfloat16* __restrict__ Xl)
{
    const size_t i = (size_t)blockIdx.x * 256 + threadIdx.x;
    float4 v = X[i];
    __nv_bfloat16 h0, h1, h2, h3, l0, l1, l2, l3;
    split1(v.x, h0, l0); split1(v.y, h1, l1);
    split1(v.z, h2, l2); split1(v.w, h3, l3);
    __nv_bfloat162 ph0 = __nv_bfloat162(h0, h1), ph1 = __nv_bfloat162(h2, h3);
    __nv_bfloat162 pl0 = __nv_bfloat162(l0, l1), pl1 = __nv_bfloat162(l2, l3);
    uint2 ph, pl;
    ph.x = *(uint32_t*)&ph0; ph.y = *(uint32_t*)&ph1;
    pl.x = *(uint32_t*)&pl0; pl.y = *(uint32_t*)&pl1;
    *(uint2*)(Xh + i * 4) = ph;
    *(uint2*)(Xl + i * 4) = pl;
}

// weights (K=256,N=256) -> transposed [N][K] hi/lo (batched over matrices)
__global__ void convw_t_kernel(const float* __restrict__ W,
                               __nv_bfloat16* __restrict__ Wh,
                               __nv_bfloat16* __restrict__ Wl)
{
    const int idx = blockIdx.x * 256 + threadIdx.x;
    const int m = idx >> 16, r = idx & 65535;
    const int k = r >> 8, n = r & 255;
    float w = W[idx];
    __nv_bfloat16 h, l; split1(w, h, l);
    const size_t o = ((size_t)m << 16) + (n << 8) + k;
    Wh[o] = h; Wl[o] = l;
}

// direct convert (already [N][K])
__global__ void convw_kernel(const float* __restrict__ W,
                             __nv_bfloat16* __restrict__ Wh,
                             __nv_bfloat16* __restrict__ Wl)
{
    const int idx = blockIdx.x * 256 + threadIdx.x;
    __nv_bfloat16 h, l; split1(W[idx], h, l);
    Wh[idx] = h; Wl[idx] = l;
}

// ----------------------------------------------------------------------------
// Window attention (fp32 in, bf16 hi/lo ctx out)
// ----------------------------------------------------------------------------
template<int WS>
__global__ __launch_bounds__(128)
void winattn_kernel(const float4* __restrict__ Q4,
                    const float4* __restrict__ K4,
                    const float4* __restrict__ V4,
                    __nv_bfloat16* __restrict__ CTXh,
                    __nv_bfloat16* __restrict__ CTXl)
{
    constexpr int WIN = WS*WS;
    constexpr int G   = 64 / WIN;
    constexpr int NW  = HIMG / WS;
    __shared__ float4 sK[2][64][9];
    __shared__ float4 sV[2][64][9];

    const int t    = threadIdx.x;
    const int slot = t >> 6;
    const int tt   = t & 63;
    const int head = blockIdx.y * 2 + slot;
    const int g    = tt / WIN;
    const int qi   = tt % WIN;
    const int widx = blockIdx.x * G + g;
    const int b    = widx / (NW*NW);
    const int rem  = widx % (NW*NW);
    const int p1   = rem / NW, p2 = rem % NW;
    const int r    = p1*WS + qi/WS;
    const int cc   = p2*WS + qi%WS;
    const int token = (b*HIMG + r)*WIMG + cc;
    const size_t base4 = (size_t)token*(CH/4) + head*(HS/4);

    float4 q[8];
    #pragma unroll
    for (int d = 0; d < 8; d++) {
        q[d]            = Q4[base4 + d];
        sK[slot][tt][d] = K4[base4 + d];
        sV[slot][tt][d] = V4[base4 + d];
    }
    __syncthreads();

    const float scale = 0.17677669529663687f;
    float sc[WIN];
    float mx = -1e30f;
    #pragma unroll
    for (int v = 0; v < WIN; v++) {
        float dot = 0.f;
        #pragma unroll
        for (int d = 0; d < 8; d++) {
            float4 k4 = sK[slot][g*WIN + v][d];
            dot += q[d].x*k4.x + q[d].y*k4.y + q[d].z*k4.z + q[d].w*k4.w;
        }
        dot *= scale;
        sc[v] = dot;
        mx = fmaxf(mx, dot);
    }
    float sum = 0.f;
    #pragma unroll
    for (int v = 0; v < WIN; v++) { sc[v] = expf(sc[v] - mx); sum += sc[v]; }
    const float inv = 1.f / sum;
    #pragma unroll
    for (int v = 0; v < WIN; v++) sc[v] *= inv;

    const size_t basee = base4 * 4;
    #pragma unroll
    for (int d = 0; d < 8; d++) {
        float4 a = make_float4(0.f, 0.f, 0.f, 0.f);
        #pragma unroll
        for (int v = 0; v < WIN; v++) {
            float4 vv = sV[slot][g*WIN + v][d];
            a.x += sc[v]*vv.x; a.y += sc[v]*vv.y;
            a.z += sc[v]*vv.z; a.w += sc[v]*vv.w;
        }
        __nv_bfloat16 h0,h1,h2,h3,l0,l1,l2,l3;
        split1(a.x,h0,l0); split1(a.y,h1,l1); split1(a.z,h2,l2); split1(a.w,h3,l3);
        __nv_bfloat162 ph0 = __nv_bfloat162(h0,h1), ph1 = __nv_bfloat162(h2,h3);
        __nv_bfloat162 pl0 = __nv_bfloat162(l0,l1), pl1 = __nv_bfloat162(l2,l3);
        uint2 ph, pl;
        ph.x = *(uint32_t*)&ph0; ph.y = *(uint32_t*)&ph1;
        pl.x = *(uint32_t*)&pl0; pl.y = *(uint32_t*)&pl1;
        *(uint2*)(CTXh + basee + d*4) = ph;
        *(uint2*)(CTXl + basee + d*4) = pl;
    }
}

// ----------------------------------------------------------------------------
// Edge conv stage 1: t9[pix,k] = sum_c x[pix,c] * w[c,k]
// ----------------------------------------------------------------------------
__global__ void conv9_kernel(const float* __restrict__ x,
                             const float* __restrict__ ew,
                             float* __restrict__ t9)
{
    __shared__ float sw[CH*9];
    const int tid = threadIdx.x;
    for (int i = tid; i < CH*9; i += 256) sw[i] = ew[i];
    __syncthreads();

    const int warp = tid >> 5, lane = tid & 31;
    const int pix = blockIdx.x * 8 + warp;
    const float4* xp = (const float4*)(x + (size_t)pix*CH) + lane*2;
    float4 v0 = xp[0], v1 = xp[1];
    float xa[8] = {v0.x,v0.y,v0.z,v0.w,v1.x,v1.y,v1.z,v1.w};

    float acc[9] = {};
    #pragma unroll
    for (int i = 0; i < 8; i++) {
        const int c = lane*8 + i;
        #pragma unroll
        for (int k = 0; k < 9; k++) acc[k] += xa[i] * sw[c*9 + k];
    }
    #pragma unroll
    for (int k = 0; k < 9; k++)
        #pragma unroll
        for (int o = 16; o; o >>= 1)
            acc[k] += __shfl_xor_sync(0xffffffffu, acc[k], o);
    if (lane < 9) t9[(size_t)pix*9 + lane] = acc[lane];
}

__global__ void edge_stencil_kernel(const float* __restrict__ t9,
                                    float* __restrict__ edge)
{
    const int pix = blockIdx.x * 256 + threadIdx.x;
    const int b = pix >> 12, y = (pix >> 6) & 63, xx = pix & 63;
    float s = 0.f;
    #pragma unroll
    for (int ky = 0; ky < 3; ky++) {
        const int yy = y + ky - 1;
        if (yy < 0 || yy > 63) continue;
        #pragma unroll
        for (int kx = 0; kx < 3; kx++) {
            const int xw = xx + kx - 1;
            if (xw < 0 || xw > 63) continue;
            s += t9[(size_t)((b*64 + yy)*64 + xw)*9 + ky*3 + kx];
        }
    }
    edge[pix] = fabsf(s);
}

__global__ void wts_kernel(const float* __restrict__ edge,
                           const float* __restrict__ w1, const float* __restrict__ b1,
                           const float* __restrict__ w2, const float* __restrict__ b2,
                           float* __restrict__ wts)
{
    int pix = blockIdx.x * blockDim.x + threadIdx.x;
    if (pix >= NTOK) return;
    int b = pix >> 12, y = (pix >> 6) & 63, xx = pix & 63;
    float s = 0.f;
    for (int dy = -1; dy <= 1; dy++) {
        int yy = y + dy; if (yy < 0 || yy > 63) continue;
        for (int dx = -1; dx <= 1; dx++) {
            int xw = xx + dx; if (xw < 0 || xw > 63) continue;
            s += edge[(b*64 + yy)*64 + xw];
        }
    }
    float e = s * (1.f/9.f);
    float lg[3] = {b2[0], b2[1], b2[2]};
    #pragma unroll
    for (int j = 0; j < 16; j++) {
        float h = fmaxf(e * w1[j] + b1[j], 0.f);
        lg[0] += h * w2[j*3 + 0];
        lg[1] += h * w2[j*3 + 1];
        lg[2] += h * w2[j*3 + 2];
    }
    float mx = fmaxf(lg[0], fmaxf(lg[1], lg[2]));
    float e0 = expf(lg[0]-mx), e1 = expf(lg[1]-mx), e2 = expf(lg[2]-mx);
    float inv = 1.f / (e0 + e1 + e2);
    wts[pix*3+0] = e0*inv;
    wts[pix*3+1] = e1*inv;
    wts[pix*3+2] = e2*inv;
}

// ----------------------------------------------------------------------------
// DlightConv (fp32 in, bf16 hi/lo out)
// ----------------------------------------------------------------------------
__global__ void dlight_kernel(const float* __restrict__ S1,
                              const float* __restrict__ dlw,
                              const float* __restrict__ dlb,
                              __nv_bfloat16* __restrict__ xdlh,
                              __nv_bfloat16* __restrict__ xdll)
{
    __shared__ float part[8][16];
    __shared__ float probs[16];
    const int bx = blockIdx.x;
    const int b = bx >> 8, p1 = (bx >> 4) & 15, p2 = bx & 15;
    const int c = threadIdx.x;

    float vals[16];
    float mean = 0.f;
    #pragma unroll
    for (int wi = 0; wi < 16; wi++) {
        int r = p1*4 + (wi >> 2), cc = p2*4 + (wi & 3);
        vals[wi] = S1[((size_t)((b*64 + r)*64 + cc))*CH + c];
        mean += vals[wi];
    }
    mean *= (1.f/16.f);

    float contrib[16];
    #pragma unroll
    for (int j = 0; j < 16; j++) contrib[j] = mean * dlw[c*16 + j];
    #pragma unroll
    for (int j = 0; j < 16; j++)
        #pragma unroll
        for (int o = 16; o; o >>= 1)
            contrib[j] += __shfl_xor_sync(0xffffffffu, contrib[j], o);
    if ((c & 31) == 0) {
        #pragma unroll
        for (int j = 0; j < 16; j++) part[c >> 5][j] = contrib[j];
    }
    __syncthreads();
    if (c == 0) {
        float lg[16], mx = -1e30f;
        #pragma unroll
        for (int j = 0; j < 16; j++) {
            float v = dlb[j];
            #pragma unroll
            for (int w = 0; w < 8; w++) v += part[w][j];
            lg[j] = v;
            mx = fmaxf(mx, v);
        }
        float sum = 0.f;
        #pragma unroll
        for (int j = 0; j < 16; j++) { lg[j] = expf(lg[j] - mx); sum += lg[j]; }
        float inv = 1.f / sum;
        #pragma unroll
        for (int j = 0; j < 16; j++) probs[j] = lg[j] * inv;
    }
    __syncthreads();
    float acc = 0.f;
    #pragma unroll
    for (int wi = 0; wi < 16; wi++) acc += vals[wi] * probs[wi];
    __nv_bfloat16 h, l; split1(acc, h, l);
    xdlh[(size_t)bx*CH + c] = h;
    xdll[(size_t)bx*CH + c] = l;
}

// ----------------------------------------------------------------------------
// Axial attention (fp32)
// ----------------------------------------------------------------------------
__global__ void axial_kernel(const float* __restrict__ Q,
                             const float* __restrict__ K,
                             const float* __restrict__ V,
                             const float* __restrict__ gsp,
                             const float* __restrict__ gbp,
                             float* __restrict__ out,
                             int axis)
{
    __shared__ float sQ[16][CH];
    __shared__ float sK[16][CH];
    __shared__ float sc[16][17];
    const int blk = blockIdx.x;
    const int b = blk >> 4, f = blk & 15;
    const int t = threadIdx.x;

    for (int idx = t; idx < 16*CH; idx += 256) {
        int i = idx >> 8, c = idx & 255;
        size_t tok = (axis == 0) ? (size_t)((b*16 + f)*16 + i)
                                 : (size_t)((b*16 + i)*16 + f);
        sQ[i][c] = Q[tok*CH + c];
        sK[i][c] = K[tok*CH + c];
    }
    __syncthreads();

    {
        int w = t >> 4, v = t & 15;
        float dot = 0.f;
        #pragma unroll 8
        for (int c = 0; c < CH; c++) dot += sQ[w][c] * sK[v][c];
        float gs = gsp[0], gb0 = gbp[0];
        float d2 = (float)((v - w) * (v - w));
        sc[w][v] = dot - (gs * d2 + gb0);
    }
    __syncthreads();
    if (t < 16) {
        float mx = -1e30f;
        #pragma unroll
        for (int v = 0; v < 16; v++) mx = fmaxf(mx, sc[t][v]);
        float sum = 0.f;
        #pragma unroll
        for (int v = 0; v < 16; v++) { float e = expf(sc[t][v] - mx); sc[t][v] = e; sum += e; }
        float inv = 1.f / sum;
        #pragma unroll
        for (int v = 0; v < 16; v++) sc[t][v] *= inv;
    }
    __syncthreads();

    const int d = t;
    float acc[16] = {};
    #pragma unroll
    for (int v = 0; v < 16; v++) {
        size_t tokv = (axis == 0) ? (size_t)((b*16 + f)*16 + v)
                                  : (size_t)((b*16 + v)*16 + f);
        float vv = V[tokv*CH + d];
        #pragma unroll
        for (int w = 0; w < 16; w++) acc[w] += sc[w][v] * vv;
    }
    #pragma unroll
    for (int w = 0; w < 16; w++) {
        size_t tokw = (axis == 0) ? (size_t)((b*16 + f)*16 + w)
                                  : (size_t)((b*16 + w)*16 + f);
        if (axis == 0) out[tokw*CH + d] = acc[w];
        else           out[tokw*CH + d] += acc[w];
    }
}

// ----------------------------------------------------------------------------
// Build Z = [upsampled x_g | blended h_map], bf16 hi/lo out
// ----------------------------------------------------------------------------
__global__ void zbuild_kernel(const float* __restrict__ xg,
                              const float* __restrict__ S0,
                              const float* __restrict__ S1,
                              const float* __restrict__ S2,
                              const float* __restrict__ wts,
                              __nv_bfloat16* __restrict__ Zh,
                              __nv_bfloat16* __restrict__ Zl)
{
    const int pix = blockIdx.x;
    const int c = threadIdx.x;
    const int b = pix >> 12, y = (pix >> 6) & 63, xx = pix & 63;
    const float scl = 15.f / 63.f;

    float pr = y * scl;
    int r0 = (int)floorf(pr);
    float tr = pr - (float)r0;
    int r1 = min(r0 + 1, 15);
    float pc = xx * scl;
    int c0 = (int)floorf(pc);
    float tc = pc - (float)c0;
    int c1 = min(c0 + 1, 15);

    size_t base = (size_t)b * 256;
    float v00 = xg[(base + r0*16 + c0)*CH + c];
    float v01 = xg[(base + r0*16 + c1)*CH + c];
    float v10 = xg[(base + r1*16 + c0)*CH + c];
    float v11 = xg[(base + r1*16 + c1)*CH + c];
    float left  = v00*(1.f-tr) + v10*tr;
    float right = v01*(1.f-tr) + v11*tr;
    float interp = left*(1.f-tc) + right*tc;

    size_t zb = (size_t)pix*512;
    __nv_bfloat16 h, l;
    split1(interp, h, l);
    Zh[zb + c] = h; Zl[zb + c] = l;

    float w0 = wts[pix*3+0], w1 = wts[pix*3+1], w2 = wts[pix*3+2];
    size_t sb = (size_t)pix*CH + c;
    float blend = w0*S0[sb] + w1*S1[sb] + w2*S2[sb];
    split1(blend, h, l);
    Zh[zb + 256 + c] = h; Zl[zb + 256 + c] = l;
}

// ----------------------------------------------------------------------------
// Host launch
// ----------------------------------------------------------------------------
extern "C" void kernel_launch(void* const* d_in, const int* in_sizes, int n_in,
                              void* d_out, int out_size)
{
    const float* x      = (const float*)d_in[0];
    const float* attn_w = (const float*)d_in[1];
    const float* attn_b = (const float*)d_in[2];
    const float* edge_w = (const float*)d_in[3];
    const float* mlp_w1 = (const float*)d_in[4];
    const float* mlp_b1 = (const float*)d_in[5];
    const float* mlp_w2 = (const float*)d_in[6];
    const float* mlp_b2 = (const float*)d_in[7];
    const float* dl_w   = (const float*)d_in[8];
    const float* dl_b   = (const float*)d_in[9];
    const float* ax_w   = (const float*)d_in[10];
    const float* ax_b   = (const float*)d_in[11];
    const float* g_sh   = (const float*)d_in[12];
    const float* g_bi   = (const float*)d_in[13];
    const float* sq_w   = (const float*)d_in[14];
    const float* sq_b   = (const float*)d_in[15];
    float* out = (float*)d_out;

    float *Qb, *Kb, *Vb, *Sb, *T9b, *EDGEb, *WTSb, *AQb, *AKb, *AVb, *XGb;
    __nv_bfloat16 *CTXh, *CTXl, *Xh, *Xl, *Zh, *Zl, *Wh, *Wl, *XDLh, *XDLl;
    cudaGetSymbolAddress((void**)&Qb,   g_Q);
    cudaGetSymbolAddress((void**)&Kb,   g_K);
    cudaGetSymbolAddress((void**)&Vb,   g_V);
    cudaGetSymbolAddress((void**)&Sb,   g_S);
    cudaGetSymbolAddress((void**)&T9b,  g_t9);
    cudaGetSymbolAddress((void**)&EDGEb,g_edge);
    cudaGetSymbolAddress((void**)&WTSb, g_wts);
    cudaGetSymbolAddress((void**)&AQb,  g_aQ);
    cudaGetSymbolAddress((void**)&AKb,  g_aK);
    cudaGetSymbolAddress((void**)&AVb,  g_aV);
    cudaGetSymbolAddress((void**)&XGb,  g_xg);
    cudaGetSymbolAddress((void**)&CTXh, g_CTXh);
    cudaGetSymbolAddress((void**)&CTXl, g_CTXl);
    cudaGetSymbolAddress((void**)&Xh,   g_xh);
    cudaGetSymbolAddress((void**)&Xl,   g_xl);
    cudaGetSymbolAddress((void**)&Zh,   g_Zh);
    cudaGetSymbolAddress((void**)&Zl,   g_Zl);
    cudaGetSymbolAddress((void**)&Wh,   g_Wh);
    cudaGetSymbolAddress((void**)&Wl,   g_Wl);
    cudaGetSymbolAddress((void**)&XDLh, g_xdlh);
    cudaGetSymbolAddress((void**)&XDLl, g_xdll);

    cudaFuncSetAttribute(gemm_mma2, cudaFuncAttributeMaxDynamicSharedMemorySize,
                         GEMM_SMEM);

    // ---- weight + activation conversions ----
    convw_t_kernel<<<12*65536/256, 256>>>(attn_w, Wh + WSLOT_ATTN, Wl + WSLOT_ATTN);
    convw_t_kernel<<<3*65536/256, 256>>>(ax_w, Wh + WSLOT_AX, Wl + WSLOT_AX);
    convw_kernel<<<256*512/256, 256>>>(sq_w, Wh + WSLOT_SQ, Wl + WSLOT_SQ);
    split4_kernel<<<NTOK*CH/4/256, 256>>>((const float4*)x, Xh, Xl);

    const dim3 attn_grid(1024, 4);

    // ---- 3 window-attention branches ----
    for (int br = 0; br < 3; br++) {
        // fused Q,K,V projection: 3 output matrices, one launch
        Tiles Tq;
        float* qkv[3] = {Qb, Kb, Vb};
        for (int m = 0; m < 3; m++) {
            Tq.t[m].ah = Xh;  Tq.t[m].al = Xl;
            Tq.t[m].bh = Wh + WSLOT_ATTN + (size_t)(br*4 + m)*65536;
            Tq.t[m].bl = Wl + WSLOT_ATTN + (size_t)(br*4 + m)*65536;
            Tq.t[m].bias = attn_b + (br*4 + m)*CH;
            Tq.t[m].out  = qkv[m];
        }
        gemm_mma2<<<dim3(6, NTOK/128), 256, GEMM_SMEM>>>(Tq, 256);

        if (br == 0)      winattn_kernel<2><<<attn_grid, 128>>>((const float4*)Qb, (const float4*)Kb, (const float4*)Vb, CTXh, CTXl);
        else if (br == 1) winattn_kernel<4><<<attn_grid, 128>>>((const float4*)Qb, (const float4*)Kb, (const float4*)Vb, CTXh, CTXl);
        else              winattn_kernel<8><<<attn_grid, 128>>>((const float4*)Qb, (const float4*)Kb, (const float4*)Vb, CTXh, CTXl);

        Tiles To;
        To.t[0].ah = CTXh; To.t[0].al = CTXl;
        To.t[0].bh = Wh + WSLOT_ATTN + (size_t)(br*4 + 3)*65536;
        To.t[0].bl = Wl + WSLOT_ATTN + (size_t)(br*4 + 3)*65536;
        To.t[0].bias = attn_b + (br*4 + 3)*CH;
        To.t[0].out  = Sb + (size_t)br*NTOK*CH;
        To.t[1] = To.t[0]; To.t[2] = To.t[0];
        gemm_mma2<<<dim3(2, NTOK/128), 256, GEMM_SMEM>>>(To, 256);
    }

    // ---- edge selector ----
    conv9_kernel<<<NTOK/8, 256>>>(x, edge_w, T9b);
    edge_stencil_kernel<<<NTOK/256, 256>>>(T9b, EDGEb);
    wts_kernel<<<NTOK/256, 256>>>(EDGEb, mlp_w1, mlp_b1, mlp_w2, mlp_b2, WTSb);

    // ---- DlightConv ----
    dlight_kernel<<<NDTOK, 256>>>(Sb + (size_t)1*NTOK*CH, dl_w, dl_b, XDLh, XDLl);

    // ---- axial projections (fused q,k,v) ----
    {
        Tiles Ta;
        float* aqkv[3] = {AQb, AKb, AVb};
        for (int m = 0; m < 3; m++) {
            Ta.t[m].ah = XDLh; Ta.t[m].al = XDLl;
            Ta.t[m].bh = Wh + WSLOT_AX + (size_t)m*65536;
            Ta.t[m].bl = Wl + WSLOT_AX + (size_t)m*65536;
            Ta.t[m].bias = ax_b + m*CH;
            Ta.t[m].out  = aqkv[m];
        }
        gemm_mma2<<<dim3(6, NDTOK/128), 256, GEMM_SMEM>>>(Ta, 256);
    }

    // ---- axial attention ----
    axial_kernel<<<BSZ*PP, 256>>>(AQb, AKb, AVb, g_sh, g_bi, XGb, 0);
    axial_kernel<<<BSZ*PP, 256>>>(AQb, AKb, AVb, g_sh, g_bi, XGb, 1);

    // ---- Z build + final projection ----
    zbuild_kernel<<<NTOK, 256>>>(XGb,
                                 Sb + (size_t)0*NTOK*CH,
                                 Sb + (size_t)1*NTOK*CH,
                                 Sb + (size_t)2*NTOK*CH,
                                 WTSb, Zh, Zl);

    {
        Tiles Tf;
        Tf.t[0].ah = Zh; Tf.t[0].al = Zl;
        Tf.t[0].bh = Wh + WSLOT_SQ; Tf.t[0].bl = Wl + WSLOT_SQ;
        Tf.t[0].bias = sq_b;
        Tf.t[0].out  = out;
        Tf.t[1] = Tf.t[0]; Tf.t[2] = Tf.t[0];
        gemm_mma2<<<dim3(2, NTOK/128), 256, GEMM_SMEM>>>(Tf, 512);
    }
}

// round 6
// speedup vs baseline: 5.2525x; 1.3352x over previous
#include <cuda_runtime.h>
#include <cuda_bf16.h>
#include <cuda_fp16.h>
#include <math.h>
#include <stdint.h>

// ----------------------------------------------------------------------------
// Problem constants
// ----------------------------------------------------------------------------
#define BSZ   16
#define HIMG  64
#define WIMG  64
#define CH    256
#define NTOK  (BSZ*HIMG*WIMG)       // 65536
#define NHEAD 8
#define HS    32
#define PP    16
#define NDTOK (BSZ*PP*PP)           // 4096

// bf16 weight slots ([N][K]); only V/O/ax-v/sq slots actually used
#define WSLOT_ATTN   0
#define WSLOT_AX     (12*65536)
#define WSLOT_SQ     (12*65536 + 3*65536)
#define WTOTAL       (WSLOT_SQ + 256*512)

// ----------------------------------------------------------------------------
// Scratch
// ----------------------------------------------------------------------------
__device__ float g_QKV[9][NTOK*CH];          // [branch*3 + {q,k,v}]
__device__ float g_S[3][NTOK*CH];
__device__ __nv_bfloat16 g_CTXh[3][NTOK*CH];
__device__ __nv_bfloat16 g_CTXl[3][NTOK*CH];
__device__ __nv_bfloat16 g_xh[NTOK*CH];
__device__ __nv_bfloat16 g_xl[NTOK*CH];
__device__ __half        g_xf[NTOK*CH];
__device__ __nv_bfloat16 g_Zh[(size_t)NTOK*2*CH];
__device__ __nv_bfloat16 g_Zl[(size_t)NTOK*2*CH];
__device__ __nv_bfloat16 g_Wh[WTOTAL];
__device__ __nv_bfloat16 g_Wl[WTOTAL];
__device__ __half        g_Wf[8*65536];      // fp16 q,k weights: 6 attn + 2 axial
__device__ __nv_bfloat16 g_xdlh[NDTOK*CH];
__device__ __nv_bfloat16 g_xdll[NDTOK*CH];
__device__ __half        g_xdlf[NDTOK*CH];
__device__ float g_t9[NTOK*9];
__device__ float g_edge[NTOK];
__device__ float g_wts[NTOK*3];
__device__ float g_aQ[NDTOK*CH];
__device__ float g_aK[NDTOK*CH];
__device__ float g_aV[NDTOK*CH];
__device__ float g_xg[NDTOK*CH];

// ----------------------------------------------------------------------------
// PTX helpers (baseline sm_80-class PTX only)
// ----------------------------------------------------------------------------
__device__ __forceinline__ uint32_t smem_u32(const void* p) {
    uint32_t a;
    asm("{ .reg .u64 t; cvta.to.shared.u64 t, %1; cvt.u32.u64 %0, t; }"
        : "=r"(a) : "l"(p));
    return a;
}
__device__ __forceinline__ void ldsm4(uint32_t* r, uint32_t addr) {
    asm volatile("ldmatrix.sync.aligned.m8n8.x4.shared.b16 {%0,%1,%2,%3}, [%4];"
                 : "=r"(r[0]), "=r"(r[1]), "=r"(r[2]), "=r"(r[3]) : "r"(addr));
}
__device__ __forceinline__ void mma_bf16(float* d, const uint32_t* a,
                                         uint32_t b0, uint32_t b1) {
    asm volatile("mma.sync.aligned.m16n8k16.row.col.f32.bf16.bf16.f32 "
                 "{%0,%1,%2,%3}, {%4,%5,%6,%7}, {%8,%9}, {%0,%1,%2,%3};"
                 : "+f"(d[0]), "+f"(d[1]), "+f"(d[2]), "+f"(d[3])
                 : "r"(a[0]), "r"(a[1]), "r"(a[2]), "r"(a[3]), "r"(b0), "r"(b1));
}
__device__ __forceinline__ void mma_f16(float* d, const uint32_t* a,
                                        uint32_t b0, uint32_t b1) {
    asm volatile("mma.sync.aligned.m16n8k16.row.col.f32.f16.f16.f32 "
                 "{%0,%1,%2,%3}, {%4,%5,%6,%7}, {%8,%9}, {%0,%1,%2,%3};"
                 : "+f"(d[0]), "+f"(d[1]), "+f"(d[2]), "+f"(d[3])
                 : "r"(a[0]), "r"(a[1]), "r"(a[2]), "r"(a[3]), "r"(b0), "r"(b1));
}
#define CP16(dst, src) \
    asm volatile("cp.async.cg.shared.global [%0], [%1], 16;" :: "r"(dst), "l"(src))
#define CP_COMMIT() asm volatile("cp.async.commit_group;" ::: "memory")
#define CP_WAIT0()  asm volatile("cp.async.wait_group 0;" ::: "memory")

// ----------------------------------------------------------------------------
// GEMM tile descriptors
// ----------------------------------------------------------------------------
struct Tile {
    const __nv_bfloat16 *ah, *al, *bh, *bl;
    const float* bias;
    float* out;
};
struct Tiles { Tile t[3]; };

struct TileH {
    const __half *a, *b;
    const float* bias;
    float* out;
};
struct TilesH { TileH t[6]; };

// bf16x3 smem layout (bytes): each chunk matrix is [128][40] bf16 = 10240 B
#define SM_AH  0
#define SM_AL  10240
#define SM_BH  20480
#define SM_BL  30720
#define SM_BUF 40960
#define GEMM_SMEM (2*SM_BUF)

// fp16 single-product smem layout
#define SMH_A  0
#define SMH_B  10240
#define SMH_BUF 20480
#define GEMMH_SMEM (2*SMH_BUF)

// ----------------------------------------------------------------------------
// bf16x3 split GEMM (Ah+Al)(Bh+Bl)^T, drop Al*Bl. Single sync per chunk.
// Block 128x128, 8 warps (4M x 2N), k-chunk 32, double-buffered cp.async.
// grid.x = 2*nmat, grid.y = M/128.
// ----------------------------------------------------------------------------
__device__ __forceinline__ void load_chunk3(
    uint32_t sbase, const Tile& e, int K, int row0, int col0, int k0, int t)
{
    const int lrow = t >> 1;
    const int lseg = (t & 1) * 16;
    const uint32_t doff = (uint32_t)(lrow * 80 + lseg * 2);
    {
        const __nv_bfloat16* s = e.ah + (size_t)(row0 + lrow) * K + k0 + lseg;
        CP16(sbase + SM_AH + doff,      s);
        CP16(sbase + SM_AH + doff + 16, s + 8);
        s = e.al + (size_t)(row0 + lrow) * K + k0 + lseg;
        CP16(sbase + SM_AL + doff,      s);
        CP16(sbase + SM_AL + doff + 16, s + 8);
    }
    {
        const __nv_bfloat16* s = e.bh + (size_t)(col0 + lrow) * K + k0 + lseg;
        CP16(sbase + SM_BH + doff,      s);
        CP16(sbase + SM_BH + doff + 16, s + 8);
        s = e.bl + (size_t)(col0 + lrow) * K + k0 + lseg;
        CP16(sbase + SM_BL + doff,      s);
        CP16(sbase + SM_BL + doff + 16, s + 8);
    }
}

__global__ __launch_bounds__(256)
void gemm_mma3(Tiles T, int K)
{
    extern __shared__ char sm[];
    const uint32_t sb0 = smem_u32(sm);

    const int t = threadIdx.x;
    const int wid = t >> 5, lane = t & 31;
    const Tile e = T.t[blockIdx.x >> 1];
    const int col0 = (blockIdx.x & 1) * 128;
    const int row0 = blockIdx.y * 128;
    const int mw = wid & 3;
    const int nw = wid >> 2;
    const int NC = K >> 5;

    float acc[2][8][4];
    #pragma unroll
    for (int i = 0; i < 2; i++)
        #pragma unroll
        for (int j = 0; j < 8; j++)
            #pragma unroll
            for (int q = 0; q < 4; q++) acc[i][j][q] = 0.f;

    load_chunk3(sb0, e, K, row0, col0, 0, t);
    CP_COMMIT();

    const uint32_t a_off[2] = {
        (uint32_t)((mw*32 + 0*16 + (lane & 15)) * 80),
        (uint32_t)((mw*32 + 1*16 + (lane & 15)) * 80)
    };
    const uint32_t a_col = (uint32_t)(((lane >> 4) << 3) * 2);
    uint32_t b_off[4];
    #pragma unroll
    for (int j = 0; j < 4; j++)
        b_off[j] = (uint32_t)((nw*64 + j*16 + (lane & 7) + ((lane >> 4) << 3)) * 80);
    const uint32_t b_col = (uint32_t)((((lane >> 3) & 1) << 3) * 2);

    for (int c = 0; c < NC; c++) {
        CP_WAIT0();
        __syncthreads();
        if (c + 1 < NC) {
            load_chunk3(sb0 + (uint32_t)((c + 1) & 1) * SM_BUF, e, K, row0, col0,
                        (c + 1) << 5, t);
            CP_COMMIT();
        }
        const uint32_t bb = sb0 + (uint32_t)(c & 1) * SM_BUF;

        #pragma unroll
        for (int ks = 0; ks < 2; ks++) {
            const uint32_t kc = (uint32_t)(ks * 32);
            uint32_t afh[2][4], afl[2][4], bfh[4][4], bfl[4][4];
            #pragma unroll
            for (int mt = 0; mt < 2; mt++) {
                ldsm4(afh[mt], bb + SM_AH + a_off[mt] + kc + a_col);
                ldsm4(afl[mt], bb + SM_AL + a_off[mt] + kc + a_col);
            }
            #pragma unroll
            for (int j = 0; j < 4; j++) {
                ldsm4(bfh[j], bb + SM_BH + b_off[j] + kc + b_col);
                ldsm4(bfl[j], bb + SM_BL + b_off[j] + kc + b_col);
            }
            #pragma unroll
            for (int mt = 0; mt < 2; mt++)
                #pragma unroll
                for (int j = 0; j < 4; j++) {
                    mma_bf16(acc[mt][2*j],     afh[mt], bfh[j][0], bfh[j][1]);
                    mma_bf16(acc[mt][2*j + 1], afh[mt], bfh[j][2], bfh[j][3]);
                    mma_bf16(acc[mt][2*j],     afh[mt], bfl[j][0], bfl[j][1]);
                    mma_bf16(acc[mt][2*j + 1], afh[mt], bfl[j][2], bfl[j][3]);
                    mma_bf16(acc[mt][2*j],     afl[mt], bfh[j][0], bfh[j][1]);
                    mma_bf16(acc[mt][2*j + 1], afl[mt], bfh[j][2], bfh[j][3]);
                }
        }
        __syncthreads();   // all warps done with buf before its next overwrite-wait
    }

    #pragma unroll
    for (int mt = 0; mt < 2; mt++) {
        const int r_ = row0 + mw*32 + mt*16 + (lane >> 2);
        #pragma unroll
        for (int j = 0; j < 8; j++) {
            const int c_ = col0 + nw*64 + j*8 + (lane & 3)*2;
            const float b0 = e.bias[c_], b1 = e.bias[c_ + 1];
            float2 v0 = make_float2(acc[mt][j][0] + b0, acc[mt][j][1] + b1);
            float2 v1 = make_float2(acc[mt][j][2] + b0, acc[mt][j][3] + b1);
            *(float2*)&e.out[(size_t)r_ * 256 + c_]       = v0;
            *(float2*)&e.out[(size_t)(r_ + 8) * 256 + c_] = v1;
        }
    }
}

// ----------------------------------------------------------------------------
// fp16 single-product GEMM: C[M,256] = A[M,K] @ B[256,K]^T + bias
// Same tiling; 1/3 the mma count; 40 KB smem -> high occupancy.
// ----------------------------------------------------------------------------
__device__ __forceinline__ void load_chunkh(
    uint32_t sbase, const TileH& e, int K, int row0, int col0, int k0, int t)
{
    const int lrow = t >> 1;
    const int lseg = (t & 1) * 16;
    const uint32_t doff = (uint32_t)(lrow * 80 + lseg * 2);
    const __half* s = e.a + (size_t)(row0 + lrow) * K + k0 + lseg;
    CP16(sbase + SMH_A + doff,      s);
    CP16(sbase + SMH_A + doff + 16, s + 8);
    s = e.b + (size_t)(col0 + lrow) * K + k0 + lseg;
    CP16(sbase + SMH_B + doff,      s);
    CP16(sbase + SMH_B + doff + 16, s + 8);
}

__global__ __launch_bounds__(256)
void gemm_h(TilesH T, int K)
{
    extern __shared__ char sm[];
    const uint32_t sb0 = smem_u32(sm);

    const int t = threadIdx.x;
    const int wid = t >> 5, lane = t & 31;
    const TileH e = T.t[blockIdx.x >> 1];
    const int col0 = (blockIdx.x & 1) * 128;
    const int row0 = blockIdx.y * 128;
    const int mw = wid & 3;
    const int nw = wid >> 2;
    const int NC = K >> 5;

    float acc[2][8][4];
    #pragma unroll
    for (int i = 0; i < 2; i++)
        #pragma unroll
        for (int j = 0; j < 8; j++)
            #pragma unroll
            for (int q = 0; q < 4; q++) acc[i][j][q] = 0.f;

    load_chunkh(sb0, e, K, row0, col0, 0, t);
    CP_COMMIT();

    const uint32_t a_off[2] = {
        (uint32_t)((mw*32 + 0*16 + (lane & 15)) * 80),
        (uint32_t)((mw*32 + 1*16 + (lane & 15)) * 80)
    };
    const uint32_t a_col = (uint32_t)(((lane >> 4) << 3) * 2);
    uint32_t b_off[4];
    #pragma unroll
    for (int j = 0; j < 4; j++)
        b_off[j] = (uint32_t)((nw*64 + j*16 + (lane & 7) + ((lane >> 4) << 3)) * 80);
    const uint32_t b_col = (uint32_t)((((lane >> 3) & 1) << 3) * 2);

    for (int c = 0; c < NC; c++) {
        CP_WAIT0();
        __syncthreads();
        if (c + 1 < NC) {
            load_chunkh(sb0 + (uint32_t)((c + 1) & 1) * SMH_BUF, e, K, row0, col0,
                        (c + 1) << 5, t);
            CP_COMMIT();
        }
        const uint32_t bb = sb0 + (uint32_t)(c & 1) * SMH_BUF;

        #pragma unroll
        for (int ks = 0; ks < 2; ks++) {
            const uint32_t kc = (uint32_t)(ks * 32);
            uint32_t af[2][4], bf[4][4];
            #pragma unroll
            for (int mt = 0; mt < 2; mt++)
                ldsm4(af[mt], bb + SMH_A + a_off[mt] + kc + a_col);
            #pragma unroll
            for (int j = 0; j < 4; j++)
                ldsm4(bf[j], bb + SMH_B + b_off[j] + kc + b_col);
            #pragma unroll
            for (int mt = 0; mt < 2; mt++)
                #pragma unroll
                for (int j = 0; j < 4; j++) {
                    mma_f16(acc[mt][2*j],     af[mt], bf[j][0], bf[j][1]);
                    mma_f16(acc[mt][2*j + 1], af[mt], bf[j][2], bf[j][3]);
                }
        }
        __syncthreads();
    }

    #pragma unroll
    for (int mt = 0; mt < 2; mt++) {
        const int r_ = row0 + mw*32 + mt*16 + (lane >> 2);
        #pragma unroll
        for (int j = 0; j < 8; j++) {
            const int c_ = col0 + nw*64 + j*8 + (lane & 3)*2;
            const float b0 = e.bias[c_], b1 = e.bias[c_ + 1];
            float2 v0 = make_float2(acc[mt][j][0] + b0, acc[mt][j][1] + b1);
            float2 v1 = make_float2(acc[mt][j][2] + b0, acc[mt][j][3] + b1);
            *(float2*)&e.out[(size_t)r_ * 256 + c_]       = v0;
            *(float2*)&e.out[(size_t)(r_ + 8) * 256 + c_] = v1;
        }
    }
}

// ----------------------------------------------------------------------------
// Conversions
// ----------------------------------------------------------------------------
__device__ __forceinline__ void split1(float v, __nv_bfloat16& h, __nv_bfloat16& l) {
    h = __float2bfloat16(v);
    l = __float2bfloat16(v - __bfloat162float(h));
}

__global__ void split4_kernel(const float4* __restrict__ X,
                              __nv_bfloat16* __restrict__ Xh,
                              __nv_bfloat16* __restrict__ Xl,
                              __half* __restrict__ Xf)
{
    const size_t i = (size_t)blockIdx.x * 256 + threadIdx.x;
    float4 v = X[i];
    __nv_bfloat16 h0, h1, h2, h3, l0, l1, l2, l3;
    split1(v.x, h0, l0); split1(v.y, h1, l1);
    split1(v.z, h2, l2); split1(v.w, h3, l3);
    __nv_bfloat162 ph0 = __nv_bfloat162(h0, h1), ph1 = __nv_bfloat162(h2, h3);
    __nv_bfloat162 pl0 = __nv_bfloat162(l0, l1), pl1 = __nv_bfloat162(l2, l3);
    uint2 ph, pl;
    ph.x = *(uint32_t*)&ph0; ph.y = *(uint32_t*)&ph1;
    pl.x = *(uint32_t*)&pl0; pl.y = *(uint32_t*)&pl1;
    *(uint2*)(Xh + i * 4) = ph;
    *(uint2*)(Xl + i * 4) = pl;
    __half2 f0 = __floats2half2_rn(v.x, v.y), f1 = __floats2half2_rn(v.z, v.w);
    uint2 pf;
    pf.x = *(uint32_t*)&f0; pf.y = *(uint32_t*)&f1;
    *(uint2*)(Xf + i * 4) = pf;
}

// weights -> transposed [N][K] bf16 hi/lo (batched)
__global__ void convw_t_kernel(const float* __restrict__ W,
                               __nv_bfloat16* __restrict__ Wh,
                               __nv_bfloat16* __restrict__ Wl)
{
    const int idx = blockIdx.x * 256 + threadIdx.x;
    const int m = idx >> 16, r = idx & 65535;
    const int k = r >> 8, n = r & 255;
    float w = W[idx];
    __nv_bfloat16 h, l; split1(w, h, l);
    const size_t o = ((size_t)m << 16) + (n << 8) + k;
    Wh[o] = h; Wl[o] = l;
}
__global__ void convw_kernel(const float* __restrict__ W,
                             __nv_bfloat16* __restrict__ Wh,
                             __nv_bfloat16* __restrict__ Wl)
{
    const int idx = blockIdx.x * 256 + threadIdx.x;
    __nv_bfloat16 h, l; split1(W[idx], h, l);
    Wh[idx] = h; Wl[idx] = l;
}

// fp16 q,k weights: attn slots (br*4+{0,1}) -> Wf[s], s = br*2 + j
__global__ void convw_qk16_kernel(const float* __restrict__ attn_w,
                                  __half* __restrict__ Wf)
{
    const int idx = blockIdx.x * 256 + threadIdx.x;
    const int s = idx >> 16, r = idx & 65535;
    const int k = r >> 8, n = r & 255;
    const int src = (4*(s >> 1) + (s & 1)) * 65536 + r;
    Wf[((size_t)s << 16) + (n << 8) + k] = __float2half(attn_w[src]);
}
// fp16 axial q,k: ax_w[0..1] -> Wf[6+s]
__global__ void convw_ax16_kernel(const float* __restrict__ ax_w,
                                  __half* __restrict__ Wf)
{
    const int idx = blockIdx.x * 256 + threadIdx.x;
    const int s = idx >> 16, r = idx & 65535;
    const int k = r >> 8, n = r & 255;
    Wf[((size_t)(6 + s) << 16) + (n << 8) + k] = __float2half(ax_w[s*65536 + r]);
}

// ----------------------------------------------------------------------------
// Window attention (fp32 in, bf16 hi/lo ctx out)
// ----------------------------------------------------------------------------
template<int WS>
__global__ __launch_bounds__(128)
void winattn_kernel(const float4* __restrict__ Q4,
                    const float4* __restrict__ K4,
                    const float4* __restrict__ V4,
                    __nv_bfloat16* __restrict__ CTXh,
                    __nv_bfloat16* __restrict__ CTXl)
{
    constexpr int WIN = WS*WS;
    constexpr int G   = 64 / WIN;
    constexpr int NW  = HIMG / WS;
    __shared__ float4 sK[2][64][9];
    __shared__ float4 sV[2][64][9];

    const int t    = threadIdx.x;
    const int slot = t >> 6;
    const int tt   = t & 63;
    const int head = blockIdx.y * 2 + slot;
    const int g    = tt / WIN;
    const int qi   = tt % WIN;
    const int widx = blockIdx.x * G + g;
    const int b    = widx / (NW*NW);
    const int rem  = widx % (NW*NW);
    const int p1   = rem / NW, p2 = rem % NW;
    const int r    = p1*WS + qi/WS;
    const int cc   = p2*WS + qi%WS;
    const int token = (b*HIMG + r)*WIMG + cc;
    const size_t base4 = (size_t)token*(CH/4) + head*(HS/4);

    float4 q[8];
    #pragma unroll
    for (int d = 0; d < 8; d++) {
        q[d]            = Q4[base4 + d];
        sK[slot][tt][d] = K4[base4 + d];
        sV[slot][tt][d] = V4[base4 + d];
    }
    __syncthreads();

    const float scale = 0.17677669529663687f;
    float sc[WIN];
    float mx = -1e30f;
    #pragma unroll
    for (int v = 0; v < WIN; v++) {
        float dot = 0.f;
        #pragma unroll
        for (int d = 0; d < 8; d++) {
            float4 k4 = sK[slot][g*WIN + v][d];
            dot += q[d].x*k4.x + q[d].y*k4.y + q[d].z*k4.z + q[d].w*k4.w;
        }
        dot *= scale;
        sc[v] = dot;
        mx = fmaxf(mx, dot);
    }
    float sum = 0.f;
    #pragma unroll
    for (int v = 0; v < WIN; v++) { sc[v] = expf(sc[v] - mx); sum += sc[v]; }
    const float inv = 1.f / sum;
    #pragma unroll
    for (int v = 0; v < WIN; v++) sc[v] *= inv;

    const size_t basee = base4 * 4;
    #pragma unroll
    for (int d = 0; d < 8; d++) {
        float4 a = make_float4(0.f, 0.f, 0.f, 0.f);
        #pragma unroll
        for (int v = 0; v < WIN; v++) {
            float4 vv = sV[slot][g*WIN + v][d];
            a.x += sc[v]*vv.x; a.y += sc[v]*vv.y;
            a.z += sc[v]*vv.z; a.w += sc[v]*vv.w;
        }
        __nv_bfloat16 h0,h1,h2,h3,l0,l1,l2,l3;
        split1(a.x,h0,l0); split1(a.y,h1,l1); split1(a.z,h2,l2); split1(a.w,h3,l3);
        __nv_bfloat162 ph0 = __nv_bfloat162(h0,h1), ph1 = __nv_bfloat162(h2,h3);
        __nv_bfloat162 pl0 = __nv_bfloat162(l0,l1), pl1 = __nv_bfloat162(l2,l3);
        uint2 ph, pl;
        ph.x = *(uint32_t*)&ph0; ph.y = *(uint32_t*)&ph1;
        pl.x = *(uint32_t*)&pl0; pl.y = *(uint32_t*)&pl1;
        *(uint2*)(CTXh + basee + d*4) = ph;
        *(uint2*)(CTXl + basee + d*4) = pl;
    }
}

// ----------------------------------------------------------------------------
// Edge selector
// ----------------------------------------------------------------------------
__global__ void conv9_kernel(const float* __restrict__ x,
                             const float* __restrict__ ew,
                             float* __restrict__ t9)
{
    __shared__ float sw[CH*9];
    const int tid = threadIdx.x;
    for (int i = tid; i < CH*9; i += 256) sw[i] = ew[i];
    __syncthreads();

    const int warp = tid >> 5, lane = tid & 31;
    const int pix = blockIdx.x * 8 + warp;
    const float4* xp = (const float4*)(x + (size_t)pix*CH) + lane*2;
    float4 v0 = xp[0], v1 = xp[1];
    float xa[8] = {v0.x,v0.y,v0.z,v0.w,v1.x,v1.y,v1.z,v1.w};

    float acc[9] = {};
    #pragma unroll
    for (int i = 0; i < 8; i++) {
        const int c = lane*8 + i;
        #pragma unroll
        for (int k = 0; k < 9; k++) acc[k] += xa[i] * sw[c*9 + k];
    }
    #pragma unroll
    for (int k = 0; k < 9; k++)
        #pragma unroll
        for (int o = 16; o; o >>= 1)
            acc[k] += __shfl_xor_sync(0xffffffffu, acc[k], o);
    if (lane < 9) t9[(size_t)pix*9 + lane] = acc[lane];
}

__global__ void edge_stencil_kernel(const float* __restrict__ t9,
                                    float* __restrict__ edge)
{
    const int pix = blockIdx.x * 256 + threadIdx.x;
    const int b = pix >> 12, y = (pix >> 6) & 63, xx = pix & 63;
    float s = 0.f;
    #pragma unroll
    for (int ky = 0; ky < 3; ky++) {
        const int yy = y + ky - 1;
        if (yy < 0 || yy > 63) continue;
        #pragma unroll
        for (int kx = 0; kx < 3; kx++) {
            const int xw = xx + kx - 1;
            if (xw < 0 || xw > 63) continue;
            s += t9[(size_t)((b*64 + yy)*64 + xw)*9 + ky*3 + kx];
        }
    }
    edge[pix] = fabsf(s);
}

__global__ void wts_kernel(const float* __restrict__ edge,
                           const float* __restrict__ w1, const float* __restrict__ b1,
                           const float* __restrict__ w2, const float* __restrict__ b2,
                           float* __restrict__ wts)
{
    int pix = blockIdx.x * blockDim.x + threadIdx.x;
    if (pix >= NTOK) return;
    int b = pix >> 12, y = (pix >> 6) & 63, xx = pix & 63;
    float s = 0.f;
    for (int dy = -1; dy <= 1; dy++) {
        int yy = y + dy; if (yy < 0 || yy > 63) continue;
        for (int dx = -1; dx <= 1; dx++) {
            int xw = xx + dx; if (xw < 0 || xw > 63) continue;
            s += edge[(b*64 + yy)*64 + xw];
        }
    }
    float e = s * (1.f/9.f);
    float lg[3] = {b2[0], b2[1], b2[2]};
    #pragma unroll
    for (int j = 0; j < 16; j++) {
        float h = fmaxf(e * w1[j] + b1[j], 0.f);
        lg[0] += h * w2[j*3 + 0];
        lg[1] += h * w2[j*3 + 1];
        lg[2] += h * w2[j*3 + 2];
    }
    float mx = fmaxf(lg[0], fmaxf(lg[1], lg[2]));
    float e0 = expf(lg[0]-mx), e1 = expf(lg[1]-mx), e2 = expf(lg[2]-mx);
    float inv = 1.f / (e0 + e1 + e2);
    wts[pix*3+0] = e0*inv;
    wts[pix*3+1] = e1*inv;
    wts[pix*3+2] = e2*inv;
}

// ----------------------------------------------------------------------------
// DlightConv (fp32 in; bf16 hi/lo + fp16 out)
// ----------------------------------------------------------------------------
__global__ void dlight_kernel(const float* __restrict__ S1,
                              const float* __restrict__ dlw,
                              const float* __restrict__ dlb,
                              __nv_bfloat16* __restrict__ xdlh,
                              __nv_bfloat16* __restrict__ xdll,
                              __half* __restrict__ xdlf)
{
    __shared__ float part[8][16];
    __shared__ float probs[16];
    const int bx = blockIdx.x;
    const int b = bx >> 8, p1 = (bx >> 4) & 15, p2 = bx & 15;
    const int c = threadIdx.x;

    float vals[16];
    float mean = 0.f;
    #pragma unroll
    for (int wi = 0; wi < 16; wi++) {
        int r = p1*4 + (wi >> 2), cc = p2*4 + (wi & 3);
        vals[wi] = S1[((size_t)((b*64 + r)*64 + cc))*CH + c];
        mean += vals[wi];
    }
    mean *= (1.f/16.f);

    float contrib[16];
    #pragma unroll
    for (int j = 0; j < 16; j++) contrib[j] = mean * dlw[c*16 + j];
    #pragma unroll
    for (int j = 0; j < 16; j++)
        #pragma unroll
        for (int o = 16; o; o >>= 1)
            contrib[j] += __shfl_xor_sync(0xffffffffu, contrib[j], o);
    if ((c & 31) == 0) {
        #pragma unroll
        for (int j = 0; j < 16; j++) part[c >> 5][j] = contrib[j];
    }
    __syncthreads();
    if (c == 0) {
        float lg[16], mx = -1e30f;
        #pragma unroll
        for (int j = 0; j < 16; j++) {
            float v = dlb[j];
            #pragma unroll
            for (int w = 0; w < 8; w++) v += part[w][j];
            lg[j] = v;
            mx = fmaxf(mx, v);
        }
        float sum = 0.f;
        #pragma unroll
        for (int j = 0; j < 16; j++) { lg[j] = expf(lg[j] - mx); sum += lg[j]; }
        float inv = 1.f / sum;
        #pragma unroll
        for (int j = 0; j < 16; j++) probs[j] = lg[j] * inv;
    }
    __syncthreads();
    float acc = 0.f;
    #pragma unroll
    for (int wi = 0; wi < 16; wi++) acc += vals[wi] * probs[wi];
    __nv_bfloat16 h, l; split1(acc, h, l);
    xdlh[(size_t)bx*CH + c] = h;
    xdll[(size_t)bx*CH + c] = l;
    xdlf[(size_t)bx*CH + c] = __float2half(acc);
}

// ----------------------------------------------------------------------------
// Axial attention (fp32)
// ----------------------------------------------------------------------------
__global__ void axial_kernel(const float* __restrict__ Q,
                             const float* __restrict__ K,
                             const float* __restrict__ V,
                             const float* __restrict__ gsp,
                             const float* __restrict__ gbp,
                             float* __restrict__ out,
                             int axis)
{
    __shared__ float sQ[16][CH];
    __shared__ float sK[16][CH];
    __shared__ float sc[16][17];
    const int blk = blockIdx.x;
    const int b = blk >> 4, f = blk & 15;
    const int t = threadIdx.x;

    for (int idx = t; idx < 16*CH; idx += 256) {
        int i = idx >> 8, c = idx & 255;
        size_t tok = (axis == 0) ? (size_t)((b*16 + f)*16 + i)
                                 : (size_t)((b*16 + i)*16 + f);
        sQ[i][c] = Q[tok*CH + c];
        sK[i][c] = K[tok*CH + c];
    }
    __syncthreads();

    {
        int w = t >> 4, v = t & 15;
        float dot = 0.f;
        #pragma unroll 8
        for (int c = 0; c < CH; c++) dot += sQ[w][c] * sK[v][c];
        float gs = gsp[0], gb0 = gbp[0];
        float d2 = (float)((v - w) * (v - w));
        sc[w][v] = dot - (gs * d2 + gb0);
    }
    __syncthreads();
    if (t < 16) {
        float mx = -1e30f;
        #pragma unroll
        for (int v = 0; v < 16; v++) mx = fmaxf(mx, sc[t][v]);
        float sum = 0.f;
        #pragma unroll
        for (int v = 0; v < 16; v++) { float e = expf(sc[t][v] - mx); sc[t][v] = e; sum += e; }
        float inv = 1.f / sum;
        #pragma unroll
        for (int v = 0; v < 16; v++) sc[t][v] *= inv;
    }
    __syncthreads();

    const int d = t;
    float acc[16] = {};
    #pragma unroll
    for (int v = 0; v < 16; v++) {
        size_t tokv = (axis == 0) ? (size_t)((b*16 + f)*16 + v)
                                  : (size_t)((b*16 + v)*16 + f);
        float vv = V[tokv*CH + d];
        #pragma unroll
        for (int w = 0; w < 16; w++) acc[w] += sc[w][v] * vv;
    }
    #pragma unroll
    for (int w = 0; w < 16; w++) {
        size_t tokw = (axis == 0) ? (size_t)((b*16 + f)*16 + w)
                                  : (size_t)((b*16 + w)*16 + f);
        if (axis == 0) out[tokw*CH + d] = acc[w];
        else           out[tokw*CH + d] += acc[w];
    }
}

// ----------------------------------------------------------------------------
// Build Z = [upsampled x_g | blended h_map], bf16 hi/lo out
// ----------------------------------------------------------------------------
__global__ void zbuild_kernel(const float* __restrict__ xg,
                              const float* __restrict__ S0,
                              const float* __restrict__ S1,
                              const float* __restrict__ S2,
                              const float* __restrict__ wts,
                              __nv_bfloat16* __restrict__ Zh,
                              __nv_bfloat16* __restrict__ Zl)
{
    const int pix = blockIdx.x;
    const int c = threadIdx.x;
    const int b = pix >> 12, y = (pix >> 6) & 63, xx = pix & 63;
    const float scl = 15.f / 63.f;

    float pr = y * scl;
    int r0 = (int)floorf(pr);
    float tr = pr - (float)r0;
    int r1 = min(r0 + 1, 15);
    float pc = xx * scl;
    int c0 = (int)floorf(pc);
    float tc = pc - (float)c0;
    int c1 = min(c0 + 1, 15);

    size_t base = (size_t)b * 256;
    float v00 = xg[(base + r0*16 + c0)*CH + c];
    float v01 = xg[(base + r0*16 + c1)*CH + c];
    float v10 = xg[(base + r1*16 + c0)*CH + c];
    float v11 = xg[(base + r1*16 + c1)*CH + c];
    float left  = v00*(1.f-tr) + v10*tr;
    float right = v01*(1.f-tr) + v11*tr;
    float interp = left*(1.f-tc) + right*tc;

    size_t zb = (size_t)pix*512;
    __nv_bfloat16 h, l;
    split1(interp, h, l);
    Zh[zb + c] = h; Zl[zb + c] = l;

    float w0 = wts[pix*3+0], w1 = wts[pix*3+1], w2 = wts[pix*3+2];
    size_t sb = (size_t)pix*CH + c;
    float blend = w0*S0[sb] + w1*S1[sb] + w2*S2[sb];
    split1(blend, h, l);
    Zh[zb + 256 + c] = h; Zl[zb + 256 + c] = l;
}

// ----------------------------------------------------------------------------
// Host launch
// ----------------------------------------------------------------------------
extern "C" void kernel_launch(void* const* d_in, const int* in_sizes, int n_in,
                              void* d_out, int out_size)
{
    const float* x      = (const float*)d_in[0];
    const float* attn_w = (const float*)d_in[1];
    const float* attn_b = (const float*)d_in[2];
    const float* edge_w = (const float*)d_in[3];
    const float* mlp_w1 = (const float*)d_in[4];
    const float* mlp_b1 = (const float*)d_in[5];
    const float* mlp_w2 = (const float*)d_in[6];
    const float* mlp_b2 = (const float*)d_in[7];
    const float* dl_w   = (const float*)d_in[8];
    const float* dl_b   = (const float*)d_in[9];
    const float* ax_w   = (const float*)d_in[10];
    const float* ax_b   = (const float*)d_in[11];
    const float* g_sh   = (const float*)d_in[12];
    const float* g_bi   = (const float*)d_in[13];
    const float* sq_w   = (const float*)d_in[14];
    const float* sq_b   = (const float*)d_in[15];
    float* out = (float*)d_out;

    float *QKVb, *Sb, *T9b, *EDGEb, *WTSb, *AQb, *AKb, *AVb, *XGb;
    __nv_bfloat16 *CTXh, *CTXl, *Xh, *Xl, *Zh, *Zl, *Wh, *Wl, *XDLh, *XDLl;
    __half *Xf, *Wf, *XDLf;
    cudaGetSymbolAddress((void**)&QKVb, g_QKV);
    cudaGetSymbolAddress((void**)&Sb,   g_S);
    cudaGetSymbolAddress((void**)&T9b,  g_t9);
    cudaGetSymbolAddress((void**)&EDGEb,g_edge);
    cudaGetSymbolAddress((void**)&WTSb, g_wts);
    cudaGetSymbolAddress((void**)&AQb,  g_aQ);
    cudaGetSymbolAddress((void**)&AKb,  g_aK);
    cudaGetSymbolAddress((void**)&AVb,  g_aV);
    cudaGetSymbolAddress((void**)&XGb,  g_xg);
    cudaGetSymbolAddress((void**)&CTXh, g_CTXh);
    cudaGetSymbolAddress((void**)&CTXl, g_CTXl);
    cudaGetSymbolAddress((void**)&Xh,   g_xh);
    cudaGetSymbolAddress((void**)&Xl,   g_xl);
    cudaGetSymbolAddress((void**)&Xf,   g_xf);
    cudaGetSymbolAddress((void**)&Zh,   g_Zh);
    cudaGetSymbolAddress((void**)&Zl,   g_Zl);
    cudaGetSymbolAddress((void**)&Wh,   g_Wh);
    cudaGetSymbolAddress((void**)&Wl,   g_Wl);
    cudaGetSymbolAddress((void**)&Wf,   g_Wf);
    cudaGetSymbolAddress((void**)&XDLh, g_xdlh);
    cudaGetSymbolAddress((void**)&XDLl, g_xdll);
    cudaGetSymbolAddress((void**)&XDLf, g_xdlf);

    cudaFuncSetAttribute(gemm_mma3, cudaFuncAttributeMaxDynamicSharedMemorySize,
                         GEMM_SMEM);
    cudaFuncSetAttribute(gemm_h, cudaFuncAttributeMaxDynamicSharedMemorySize,
                         GEMMH_SMEM);

    // ---- conversions ----
    convw_t_kernel<<<12*65536/256, 256>>>(attn_w, Wh + WSLOT_ATTN, Wl + WSLOT_ATTN);
    convw_t_kernel<<<3*65536/256, 256>>>(ax_w, Wh + WSLOT_AX, Wl + WSLOT_AX);
    convw_kernel<<<256*512/256, 256>>>(sq_w, Wh + WSLOT_SQ, Wl + WSLOT_SQ);
    convw_qk16_kernel<<<6*65536/256, 256>>>(attn_w, Wf);
    convw_ax16_kernel<<<2*65536/256, 256>>>(ax_w, Wf);
    split4_kernel<<<NTOK*CH/4/256, 256>>>((const float4*)x, Xh, Xl, Xf);

    // ---- fused Q,K projections (fp16, 6 matrices) ----
    {
        TilesH Th;
        for (int br = 0; br < 3; br++)
            for (int j = 0; j < 2; j++) {
                const int s = br*2 + j;
                Th.t[s].a = Xf;
                Th.t[s].b = Wf + (size_t)s*65536;
                Th.t[s].bias = attn_b + (br*4 + j)*CH;
                Th.t[s].out  = QKVb + (size_t)(br*3 + j)*NTOK*CH;
            }
        gemm_h<<<dim3(12, NTOK/128), 256, GEMMH_SMEM>>>(Th, 256);
    }
    // ---- fused V projections (bf16x3, 3 matrices) ----
    {
        Tiles Tv;
        for (int br = 0; br < 3; br++) {
            Tv.t[br].ah = Xh; Tv.t[br].al = Xl;
            Tv.t[br].bh = Wh + WSLOT_ATTN + (size_t)(br*4 + 2)*65536;
            Tv.t[br].bl = Wl + WSLOT_ATTN + (size_t)(br*4 + 2)*65536;
            Tv.t[br].bias = attn_b + (br*4 + 2)*CH;
            Tv.t[br].out  = QKVb + (size_t)(br*3 + 2)*NTOK*CH;
        }
        gemm_mma3<<<dim3(6, NTOK/128), 256, GEMM_SMEM>>>(Tv, 256);
    }

    // ---- window attention per branch ----
    const dim3 attn_grid(1024, 4);
    {
        const float4* Q0 = (const float4*)(QKVb + (size_t)0*NTOK*CH);
        const float4* K0 = (const float4*)(QKVb + (size_t)1*NTOK*CH);
        const float4* V0 = (const float4*)(QKVb + (size_t)2*NTOK*CH);
        winattn_kernel<2><<<attn_grid, 128>>>(Q0, K0, V0,
            CTXh + (size_t)0*NTOK*CH, CTXl + (size_t)0*NTOK*CH);
        const float4* Q1 = (const float4*)(QKVb + (size_t)3*NTOK*CH);
        const float4* K1 = (const float4*)(QKVb + (size_t)4*NTOK*CH);
        const float4* V1 = (const float4*)(QKVb + (size_t)5*NTOK*CH);
        winattn_kernel<4><<<attn_grid, 128>>>(Q1, K1, V1,
            CTXh + (size_t)1*NTOK*CH, CTXl + (size_t)1*NTOK*CH);
        const float4* Q2 = (const float4*)(QKVb + (size_t)6*NTOK*CH);
        const float4* K2 = (const float4*)(QKVb + (size_t)7*NTOK*CH);
        const float4* V2 = (const float4*)(QKVb + (size_t)8*NTOK*CH);
        winattn_kernel<8><<<attn_grid, 128>>>(Q2, K2, V2,
            CTXh + (size_t)2*NTOK*CH, CTXl + (size_t)2*NTOK*CH);
    }

    // ---- fused out-projections (bf16x3, 3 matrices) ----
    {
        Tiles To;
        for (int br = 0; br < 3; br++) {
            To.t[br].ah = CTXh + (size_t)br*NTOK*CH;
            To.t[br].al = CTXl + (size_t)br*NTOK*CH;
            To.t[br].bh = Wh + WSLOT_ATTN + (size_t)(br*4 + 3)*65536;
            To.t[br].bl = Wl + WSLOT_ATTN + (size_t)(br*4 + 3)*65536;
            To.t[br].bias = attn_b + (br*4 + 3)*CH;
            To.t[br].out  = Sb + (size_t)br*NTOK*CH;
        }
        gemm_mma3<<<dim3(6, NTOK/128), 256, GEMM_SMEM>>>(To, 256);
    }

    // ---- edge selector ----
    conv9_kernel<<<NTOK/8, 256>>>(x, edge_w, T9b);
    edge_stencil_kernel<<<NTOK/256, 256>>>(T9b, EDGEb);
    wts_kernel<<<NTOK/256, 256>>>(EDGEb, mlp_w1, mlp_b1, mlp_w2, mlp_b2, WTSb);

    // ---- DlightConv ----
    dlight_kernel<<<NDTOK, 256>>>(Sb + (size_t)1*NTOK*CH, dl_w, dl_b,
                                  XDLh, XDLl, XDLf);

    // ---- axial projections: q,k fp16; v bf16x3 ----
    {
        TilesH Ta;
        for (int j = 0; j < 2; j++) {
            Ta.t[j].a = XDLf;
            Ta.t[j].b = Wf + (size_t)(6 + j)*65536;
            Ta.t[j].bias = ax_b + j*CH;
            Ta.t[j].out  = (j == 0) ? AQb : AKb;
        }
        gemm_h<<<dim3(4, NDTOK/128), 256, GEMMH_SMEM>>>(Ta, 256);

        Tiles Tv;
        Tv.t[0].ah = XDLh; Tv.t[0].al = XDLl;
        Tv.t[0].bh = Wh + WSLOT_AX + (size_t)2*65536;
        Tv.t[0].bl = Wl + WSLOT_AX + (size_t)2*65536;
        Tv.t[0].bias = ax_b + 2*CH;
        Tv.t[0].out  = AVb;
        Tv.t[1] = Tv.t[0]; Tv.t[2] = Tv.t[0];
        gemm_mma3<<<dim3(2, NDTOK/128), 256, GEMM_SMEM>>>(Tv, 256);
    }

    // ---- axial attention ----
    axial_kernel<<<BSZ*PP, 256>>>(AQb, AKb, AVb, g_sh, g_bi, XGb, 0);
    axial_kernel<<<BSZ*PP, 256>>>(AQb, AKb, AVb, g_sh, g_bi, XGb, 1);

    // ---- Z build + final projection ----
    zbuild_kernel<<<NTOK, 256>>>(XGb,
                                 Sb + (size_t)0*NTOK*CH,
                                 Sb + (size_t)1*NTOK*CH,
                                 Sb + (size_t)2*NTOK*CH,
                                 WTSb, Zh, Zl);
    {
        Tiles Tf;
        Tf.t[0].ah = Zh; Tf.t[0].al = Zl;
        Tf.t[0].bh = Wh + WSLOT_SQ; Tf.t[0].bl = Wl + WSLOT_SQ;
        Tf.t[0].bias = sq_b;
        Tf.t[0].out  = out;
        Tf.t[1] = Tf.t[0]; Tf.t[2] = Tf.t[0];
        gemm_mma3<<<dim3(2, NTOK/128), 256, GEMM_SMEM>>>(Tf, 512);
    }
}

// round 7
// speedup vs baseline: 7.5579x; 1.4389x over previous
#include <cuda_runtime.h>
#include <cuda_fp16.h>
#include <math.h>
#include <stdint.h>

// ----------------------------------------------------------------------------
// Problem constants
// ----------------------------------------------------------------------------
#define BSZ   16
#define HIMG  64
#define WIMG  64
#define CH    256
#define NTOK  (BSZ*HIMG*WIMG)       // 65536
#define NHEAD 8
#define HS    32
#define PP    16
#define NDTOK (BSZ*PP*PP)           // 4096

// fp16 weight slots ([N][K]): 12 attn + 3 axial + sq(256x512)
#define WF_ATTN 0
#define WF_AX   (12*65536)
#define WF_SQ   (15*65536)
#define WFTOT   (WF_SQ + 256*512)

// ----------------------------------------------------------------------------
// Scratch (all activations fp16 except axial/pooled fp32 path)
// ----------------------------------------------------------------------------
__device__ __half g_QKV[9][NTOK*CH];        // [branch*3 + {q,k,v}]
__device__ __half g_CTX[3][NTOK*CH];
__device__ __half g_S[3][NTOK*CH];
__device__ __half g_xf[NTOK*CH];
__device__ __half g_Zf[(size_t)NTOK*2*CH];
__device__ __half g_Wf[WFTOT];
__device__ __half g_xdlf[NDTOK*CH];
__device__ float  g_t9[NTOK*9];
__device__ float  g_edge[NTOK];
__device__ float  g_wts[NTOK*3];
__device__ float  g_aQ[NDTOK*CH];
__device__ float  g_aK[NDTOK*CH];
__device__ float  g_aV[NDTOK*CH];
__device__ float  g_xg[NDTOK*CH];

// ----------------------------------------------------------------------------
// PTX helpers (baseline sm_80-class PTX only)
// ----------------------------------------------------------------------------
__device__ __forceinline__ uint32_t smem_u32(const void* p) {
    uint32_t a;
    asm("{ .reg .u64 t; cvta.to.shared.u64 t, %1; cvt.u32.u64 %0, t; }"
        : "=r"(a) : "l"(p));
    return a;
}
__device__ __forceinline__ void ldsm4(uint32_t* r, uint32_t addr) {
    asm volatile("ldmatrix.sync.aligned.m8n8.x4.shared.b16 {%0,%1,%2,%3}, [%4];"
                 : "=r"(r[0]), "=r"(r[1]), "=r"(r[2]), "=r"(r[3]) : "r"(addr));
}
__device__ __forceinline__ void mma_f16(float* d, const uint32_t* a,
                                        uint32_t b0, uint32_t b1) {
    asm volatile("mma.sync.aligned.m16n8k16.row.col.f32.f16.f16.f32 "
                 "{%0,%1,%2,%3}, {%4,%5,%6,%7}, {%8,%9}, {%0,%1,%2,%3};"
                 : "+f"(d[0]), "+f"(d[1]), "+f"(d[2]), "+f"(d[3])
                 : "r"(a[0]), "r"(a[1]), "r"(a[2]), "r"(a[3]), "r"(b0), "r"(b1));
}
#define CP16(dst, src) \
    asm volatile("cp.async.cg.shared.global [%0], [%1], 16;" :: "r"(dst), "l"(src))
#define CP_COMMIT() asm volatile("cp.async.commit_group;" ::: "memory")
#define CP_WAIT0()  asm volatile("cp.async.wait_group 0;" ::: "memory")

// half <-> float pack helpers
__device__ __forceinline__ void u4_to_f4x2(uint4 r, float4& a, float4& b) {
    __half2 h0 = *(__half2*)&r.x, h1 = *(__half2*)&r.y;
    __half2 h2 = *(__half2*)&r.z, h3 = *(__half2*)&r.w;
    float2 f0 = __half22float2(h0), f1 = __half22float2(h1);
    float2 f2 = __half22float2(h2), f3 = __half22float2(h3);
    a = make_float4(f0.x, f0.y, f1.x, f1.y);
    b = make_float4(f2.x, f2.y, f3.x, f3.y);
}
__device__ __forceinline__ uint4 f4x2_to_u4(float4 a, float4 b) {
    __half2 h0 = __floats2half2_rn(a.x, a.y), h1 = __floats2half2_rn(a.z, a.w);
    __half2 h2 = __floats2half2_rn(b.x, b.y), h3 = __floats2half2_rn(b.z, b.w);
    uint4 r;
    r.x = *(uint32_t*)&h0; r.y = *(uint32_t*)&h1;
    r.z = *(uint32_t*)&h2; r.w = *(uint32_t*)&h3;
    return r;
}

// output store helpers (fp32 or fp16 epilogue)
__device__ __forceinline__ void store2(float* p, float a, float b) {
    *(float2*)p = make_float2(a, b);
}
__device__ __forceinline__ void store2(__half* p, float a, float b) {
    *(__half2*)p = __floats2half2_rn(a, b);
}

// ----------------------------------------------------------------------------
// fp16 GEMM: out[m][M,256] = A[M,K] @ B[256,K]^T + bias
// Block 128x128, 8 warps (4M x 2N), k-chunk 32, double-buffered cp.async.
// grid.x = 2*NM (tile = blockIdx.x>>1, col half = blockIdx.x&1), grid.y = M/128.
// ----------------------------------------------------------------------------
template<typename OT> struct TileT {
    const __half *a, *b;
    const float* bias;
    OT* out;
};
template<typename OT, int NM> struct TilesT { TileT<OT> t[NM]; };

#define SMH_A   0
#define SMH_B   10240
#define SMH_BUF 20480

template<typename OT>
__device__ __forceinline__ void load_chunkh(
    uint32_t sbase, const TileT<OT>& e, int K, int row0, int col0, int k0, int t)
{
    const int lrow = t >> 1;
    const int lseg = (t & 1) * 16;
    const uint32_t doff = (uint32_t)(lrow * 80 + lseg * 2);
    const __half* s = e.a + (size_t)(row0 + lrow) * K + k0 + lseg;
    CP16(sbase + SMH_A + doff,      s);
    CP16(sbase + SMH_A + doff + 16, s + 8);
    s = e.b + (size_t)(col0 + lrow) * K + k0 + lseg;
    CP16(sbase + SMH_B + doff,      s);
    CP16(sbase + SMH_B + doff + 16, s + 8);
}

template<typename OT, int NM>
__global__ __launch_bounds__(256)
void gemm_h(TilesT<OT, NM> T, int K)
{
    extern __shared__ char sm[];
    const uint32_t sb0 = smem_u32(sm);

    const int t = threadIdx.x;
    const int wid = t >> 5, lane = t & 31;
    const TileT<OT> e = T.t[blockIdx.x >> 1];
    const int col0 = (blockIdx.x & 1) * 128;
    const int row0 = blockIdx.y * 128;
    const int mw = wid & 3;
    const int nw = wid >> 2;
    const int NC = K >> 5;

    float acc[2][8][4];
    #pragma unroll
    for (int i = 0; i < 2; i++)
        #pragma unroll
        for (int j = 0; j < 8; j++)
            #pragma unroll
            for (int q = 0; q < 4; q++) acc[i][j][q] = 0.f;

    load_chunkh(sb0, e, K, row0, col0, 0, t);
    CP_COMMIT();

    const uint32_t a_off[2] = {
        (uint32_t)((mw*32 + 0*16 + (lane & 15)) * 80),
        (uint32_t)((mw*32 + 1*16 + (lane & 15)) * 80)
    };
    const uint32_t a_col = (uint32_t)(((lane >> 4) << 3) * 2);
    uint32_t b_off[4];
    #pragma unroll
    for (int j = 0; j < 4; j++)
        b_off[j] = (uint32_t)((nw*64 + j*16 + (lane & 7) + ((lane >> 4) << 3)) * 80);
    const uint32_t b_col = (uint32_t)((((lane >> 3) & 1) << 3) * 2);

    for (int c = 0; c < NC; c++) {
        CP_WAIT0();
        __syncthreads();
        if (c + 1 < NC) {
            load_chunkh(sb0 + (uint32_t)((c + 1) & 1) * SMH_BUF, e, K, row0, col0,
                        (c + 1) << 5, t);
            CP_COMMIT();
        }
        const uint32_t bb = sb0 + (uint32_t)(c & 1) * SMH_BUF;

        #pragma unroll
        for (int ks = 0; ks < 2; ks++) {
            const uint32_t kc = (uint32_t)(ks * 32);
            uint32_t af[2][4], bf[4][4];
            #pragma unroll
            for (int mt = 0; mt < 2; mt++)
                ldsm4(af[mt], bb + SMH_A + a_off[mt] + kc + a_col);
            #pragma unroll
            for (int j = 0; j < 4; j++)
                ldsm4(bf[j], bb + SMH_B + b_off[j] + kc + b_col);
            #pragma unroll
            for (int mt = 0; mt < 2; mt++)
                #pragma unroll
                for (int j = 0; j < 4; j++) {
                    mma_f16(acc[mt][2*j],     af[mt], bf[j][0], bf[j][1]);
                    mma_f16(acc[mt][2*j + 1], af[mt], bf[j][2], bf[j][3]);
                }
        }
        __syncthreads();
    }

    #pragma unroll
    for (int mt = 0; mt < 2; mt++) {
        const int r_ = row0 + mw*32 + mt*16 + (lane >> 2);
        #pragma unroll
        for (int j = 0; j < 8; j++) {
            const int c_ = col0 + nw*64 + j*8 + (lane & 3)*2;
            const float b0 = e.bias[c_], b1 = e.bias[c_ + 1];
            store2(&e.out[(size_t)r_ * 256 + c_],       acc[mt][j][0] + b0, acc[mt][j][1] + b1);
            store2(&e.out[(size_t)(r_ + 8) * 256 + c_], acc[mt][j][2] + b0, acc[mt][j][3] + b1);
        }
    }
}

// ----------------------------------------------------------------------------
// Conversions
// ----------------------------------------------------------------------------
__global__ void convw_t16(const float* __restrict__ attn_w,
                          const float* __restrict__ ax_w,
                          __half* __restrict__ Wf)
{
    const int idx = blockIdx.x * 256 + threadIdx.x;   // 15*65536
    const int m = idx >> 16, r = idx & 65535;
    const int k = r >> 8, n = r & 255;
    const float w = (m < 12) ? attn_w[idx] : ax_w[(m - 12)*65536 + r];
    Wf[((size_t)m << 16) + (n << 8) + k] = __float2half(w);
}
__global__ void convw_sq16(const float* __restrict__ sq_w, __half* __restrict__ Wf)
{
    const int idx = blockIdx.x * 256 + threadIdx.x;   // 256*512
    Wf[idx] = __float2half(sq_w[idx]);
}
__global__ void xtoh_kernel(const float4* __restrict__ X, __half* __restrict__ Xf)
{
    const size_t i = (size_t)blockIdx.x * 256 + threadIdx.x;
    float4 v = X[i];
    __half2 a = __floats2half2_rn(v.x, v.y), b = __floats2half2_rn(v.z, v.w);
    uint2 p;
    p.x = *(uint32_t*)&a; p.y = *(uint32_t*)&b;
    *(uint2*)(Xf + i * 4) = p;
}

// ----------------------------------------------------------------------------
// Window attention (fp16 in, fp16 ctx out; fp32 math inside)
// ----------------------------------------------------------------------------
template<int WS>
__global__ __launch_bounds__(128)
void winattn_kernel(const uint4* __restrict__ Q8,
                    const uint4* __restrict__ K8,
                    const uint4* __restrict__ V8,
                    uint4* __restrict__ C8)
{
    constexpr int WIN = WS*WS;
    constexpr int G   = 64 / WIN;
    constexpr int NW  = HIMG / WS;
    __shared__ float4 sK[2][64][9];
    __shared__ float4 sV[2][64][9];

    const int t    = threadIdx.x;
    const int slot = t >> 6;
    const int tt   = t & 63;
    const int head = blockIdx.y * 2 + slot;
    const int g    = tt / WIN;
    const int qi   = tt % WIN;
    const int widx = blockIdx.x * G + g;
    const int b    = widx / (NW*NW);
    const int rem  = widx % (NW*NW);
    const int p1   = rem / NW, p2 = rem % NW;
    const int r    = p1*WS + qi/WS;
    const int cc   = p2*WS + qi%WS;
    const int token = (b*HIMG + r)*WIMG + cc;
    const size_t base8 = (size_t)token*(CH/8) + head*(HS/8);   // uint4 units

    float4 q[8];
    #pragma unroll
    for (int d = 0; d < 4; d++) {
        u4_to_f4x2(Q8[base8 + d], q[2*d], q[2*d + 1]);
        float4 ka, kb, va, vb;
        u4_to_f4x2(K8[base8 + d], ka, kb);
        u4_to_f4x2(V8[base8 + d], va, vb);
        sK[slot][tt][2*d] = ka; sK[slot][tt][2*d + 1] = kb;
        sV[slot][tt][2*d] = va; sV[slot][tt][2*d + 1] = vb;
    }
    __syncthreads();

    const float scale = 0.17677669529663687f;   // 1/sqrt(32)
    float sc[WIN];
    float mx = -1e30f;
    #pragma unroll
    for (int v = 0; v < WIN; v++) {
        float dot = 0.f;
        #pragma unroll
        for (int d = 0; d < 8; d++) {
            float4 k4 = sK[slot][g*WIN + v][d];
            dot += q[d].x*k4.x + q[d].y*k4.y + q[d].z*k4.z + q[d].w*k4.w;
        }
        dot *= scale;
        sc[v] = dot;
        mx = fmaxf(mx, dot);
    }
    float sum = 0.f;
    #pragma unroll
    for (int v = 0; v < WIN; v++) { sc[v] = expf(sc[v] - mx); sum += sc[v]; }
    const float inv = 1.f / sum;
    #pragma unroll
    for (int v = 0; v < WIN; v++) sc[v] *= inv;

    #pragma unroll
    for (int dd = 0; dd < 4; dd++) {
        float4 a0 = make_float4(0.f, 0.f, 0.f, 0.f);
        float4 a1 = make_float4(0.f, 0.f, 0.f, 0.f);
        #pragma unroll
        for (int v = 0; v < WIN; v++) {
            float4 v0 = sV[slot][g*WIN + v][2*dd];
            float4 v1 = sV[slot][g*WIN + v][2*dd + 1];
            a0.x += sc[v]*v0.x; a0.y += sc[v]*v0.y;
            a0.z += sc[v]*v0.z; a0.w += sc[v]*v0.w;
            a1.x += sc[v]*v1.x; a1.y += sc[v]*v1.y;
            a1.z += sc[v]*v1.z; a1.w += sc[v]*v1.w;
        }
        C8[base8 + dd] = f4x2_to_u4(a0, a1);
    }
}

// ----------------------------------------------------------------------------
// Edge selector (reads fp32 x)
// ----------------------------------------------------------------------------
__global__ void conv9_kernel(const float* __restrict__ x,
                             const float* __restrict__ ew,
                             float* __restrict__ t9)
{
    __shared__ float sw[CH*9];
    const int tid = threadIdx.x;
    for (int i = tid; i < CH*9; i += 256) sw[i] = ew[i];
    __syncthreads();

    const int warp = tid >> 5, lane = tid & 31;
    const int pix = blockIdx.x * 8 + warp;
    const float4* xp = (const float4*)(x + (size_t)pix*CH) + lane*2;
    float4 v0 = xp[0], v1 = xp[1];
    float xa[8] = {v0.x,v0.y,v0.z,v0.w,v1.x,v1.y,v1.z,v1.w};

    float acc[9] = {};
    #pragma unroll
    for (int i = 0; i < 8; i++) {
        const int c = lane*8 + i;
        #pragma unroll
        for (int k = 0; k < 9; k++) acc[k] += xa[i] * sw[c*9 + k];
    }
    #pragma unroll
    for (int k = 0; k < 9; k++)
        #pragma unroll
        for (int o = 16; o; o >>= 1)
            acc[k] += __shfl_xor_sync(0xffffffffu, acc[k], o);
    if (lane < 9) t9[(size_t)pix*9 + lane] = acc[lane];
}

__global__ void edge_stencil_kernel(const float* __restrict__ t9,
                                    float* __restrict__ edge)
{
    const int pix = blockIdx.x * 256 + threadIdx.x;
    const int b = pix >> 12, y = (pix >> 6) & 63, xx = pix & 63;
    float s = 0.f;
    #pragma unroll
    for (int ky = 0; ky < 3; ky++) {
        const int yy = y + ky - 1;
        if (yy < 0 || yy > 63) continue;
        #pragma unroll
        for (int kx = 0; kx < 3; kx++) {
            const int xw = xx + kx - 1;
            if (xw < 0 || xw > 63) continue;
            s += t9[(size_t)((b*64 + yy)*64 + xw)*9 + ky*3 + kx];
        }
    }
    edge[pix] = fabsf(s);
}

__global__ void wts_kernel(const float* __restrict__ edge,
                           const float* __restrict__ w1, const float* __restrict__ b1,
                           const float* __restrict__ w2, const float* __restrict__ b2,
                           float* __restrict__ wts)
{
    int pix = blockIdx.x * blockDim.x + threadIdx.x;
    if (pix >= NTOK) return;
    int b = pix >> 12, y = (pix >> 6) & 63, xx = pix & 63;
    float s = 0.f;
    for (int dy = -1; dy <= 1; dy++) {
        int yy = y + dy; if (yy < 0 || yy > 63) continue;
        for (int dx = -1; dx <= 1; dx++) {
            int xw = xx + dx; if (xw < 0 || xw > 63) continue;
            s += edge[(b*64 + yy)*64 + xw];
        }
    }
    float e = s * (1.f/9.f);
    float lg[3] = {b2[0], b2[1], b2[2]};
    #pragma unroll
    for (int j = 0; j < 16; j++) {
        float h = fmaxf(e * w1[j] + b1[j], 0.f);
        lg[0] += h * w2[j*3 + 0];
        lg[1] += h * w2[j*3 + 1];
        lg[2] += h * w2[j*3 + 2];
    }
    float mx = fmaxf(lg[0], fmaxf(lg[1], lg[2]));
    float e0 = expf(lg[0]-mx), e1 = expf(lg[1]-mx), e2 = expf(lg[2]-mx);
    float inv = 1.f / (e0 + e1 + e2);
    wts[pix*3+0] = e0*inv;
    wts[pix*3+1] = e1*inv;
    wts[pix*3+2] = e2*inv;
}

// ----------------------------------------------------------------------------
// DlightConv (fp16 S1 in, fp16 out; fp32 math)
// ----------------------------------------------------------------------------
__global__ void dlight_kernel(const __half* __restrict__ S1,
                              const float* __restrict__ dlw,
                              const float* __restrict__ dlb,
                              __half* __restrict__ xdlf)
{
    __shared__ float part[8][16];
    __shared__ float probs[16];
    const int bx = blockIdx.x;
    const int b = bx >> 8, p1 = (bx >> 4) & 15, p2 = bx & 15;
    const int c = threadIdx.x;

    float vals[16];
    float mean = 0.f;
    #pragma unroll
    for (int wi = 0; wi < 16; wi++) {
        int r = p1*4 + (wi >> 2), cc = p2*4 + (wi & 3);
        vals[wi] = __half2float(S1[((size_t)((b*64 + r)*64 + cc))*CH + c]);
        mean += vals[wi];
    }
    mean *= (1.f/16.f);

    float contrib[16];
    #pragma unroll
    for (int j = 0; j < 16; j++) contrib[j] = mean * dlw[c*16 + j];
    #pragma unroll
    for (int j = 0; j < 16; j++)
        #pragma unroll
        for (int o = 16; o; o >>= 1)
            contrib[j] += __shfl_xor_sync(0xffffffffu, contrib[j], o);
    if ((c & 31) == 0) {
        #pragma unroll
        for (int j = 0; j < 16; j++) part[c >> 5][j] = contrib[j];
    }
    __syncthreads();
    if (c == 0) {
        float lg[16], mx = -1e30f;
        #pragma unroll
        for (int j = 0; j < 16; j++) {
            float v = dlb[j];
            #pragma unroll
            for (int w = 0; w < 8; w++) v += part[w][j];
            lg[j] = v;
            mx = fmaxf(mx, v);
        }
        float sum = 0.f;
        #pragma unroll
        for (int j = 0; j < 16; j++) { lg[j] = expf(lg[j] - mx); sum += lg[j]; }
        float inv = 1.f / sum;
        #pragma unroll
        for (int j = 0; j < 16; j++) probs[j] = lg[j] * inv;
    }
    __syncthreads();
    float acc = 0.f;
    #pragma unroll
    for (int wi = 0; wi < 16; wi++) acc += vals[wi] * probs[wi];
    xdlf[(size_t)bx*CH + c] = __float2half(acc);
}

// ----------------------------------------------------------------------------
// Axial attention (fp32)
// ----------------------------------------------------------------------------
__global__ void axial_kernel(const float* __restrict__ Q,
                             const float* __restrict__ K,
                             const float* __restrict__ V,
                             const float* __restrict__ gsp,
                             const float* __restrict__ gbp,
                             float* __restrict__ out,
                             int axis)
{
    __shared__ float sQ[16][CH];
    __shared__ float sK[16][CH];
    __shared__ float sc[16][17];
    const int blk = blockIdx.x;
    const int b = blk >> 4, f = blk & 15;
    const int t = threadIdx.x;

    for (int idx = t; idx < 16*CH; idx += 256) {
        int i = idx >> 8, c = idx & 255;
        size_t tok = (axis == 0) ? (size_t)((b*16 + f)*16 + i)
                                 : (size_t)((b*16 + i)*16 + f);
        sQ[i][c] = Q[tok*CH + c];
        sK[i][c] = K[tok*CH + c];
    }
    __syncthreads();

    {
        int w = t >> 4, v = t & 15;
        float dot = 0.f;
        #pragma unroll 8
        for (int c = 0; c < CH; c++) dot += sQ[w][c] * sK[v][c];
        float gs = gsp[0], gb0 = gbp[0];
        float d2 = (float)((v - w) * (v - w));
        sc[w][v] = dot - (gs * d2 + gb0);
    }
    __syncthreads();
    if (t < 16) {
        float mx = -1e30f;
        #pragma unroll
        for (int v = 0; v < 16; v++) mx = fmaxf(mx, sc[t][v]);
        float sum = 0.f;
        #pragma unroll
        for (int v = 0; v < 16; v++) { float e = expf(sc[t][v] - mx); sc[t][v] = e; sum += e; }
        float inv = 1.f / sum;
        #pragma unroll
        for (int v = 0; v < 16; v++) sc[t][v] *= inv;
    }
    __syncthreads();

    const int d = t;
    float acc[16] = {};
    #pragma unroll
    for (int v = 0; v < 16; v++) {
        size_t tokv = (axis == 0) ? (size_t)((b*16 + f)*16 + v)
                                  : (size_t)((b*16 + v)*16 + f);
        float vv = V[tokv*CH + d];
        #pragma unroll
        for (int w = 0; w < 16; w++) acc[w] += sc[w][v] * vv;
    }
    #pragma unroll
    for (int w = 0; w < 16; w++) {
        size_t tokw = (axis == 0) ? (size_t)((b*16 + f)*16 + w)
                                  : (size_t)((b*16 + w)*16 + f);
        if (axis == 0) out[tokw*CH + d] = acc[w];
        else           out[tokw*CH + d] += acc[w];
    }
}

// ----------------------------------------------------------------------------
// Build Z = [upsampled x_g | blended h_map], fp16 out
// ----------------------------------------------------------------------------
__global__ void zbuild_kernel(const float* __restrict__ xg,
                              const __half* __restrict__ S0,
                              const __half* __restrict__ S1,
                              const __half* __restrict__ S2,
                              const float* __restrict__ wts,
                              __half* __restrict__ Zf)
{
    const int pix = blockIdx.x;
    const int c = threadIdx.x;
    const int b = pix >> 12, y = (pix >> 6) & 63, xx = pix & 63;
    const float scl = 15.f / 63.f;

    float pr = y * scl;
    int r0 = (int)floorf(pr);
    float tr = pr - (float)r0;
    int r1 = min(r0 + 1, 15);
    float pc = xx * scl;
    int c0 = (int)floorf(pc);
    float tc = pc - (float)c0;
    int c1 = min(c0 + 1, 15);

    size_t base = (size_t)b * 256;
    float v00 = xg[(base + r0*16 + c0)*CH + c];
    float v01 = xg[(base + r0*16 + c1)*CH + c];
    float v10 = xg[(base + r1*16 + c0)*CH + c];
    float v11 = xg[(base + r1*16 + c1)*CH + c];
    float left  = v00*(1.f-tr) + v10*tr;
    float right = v01*(1.f-tr) + v11*tr;
    float interp = left*(1.f-tc) + right*tc;

    size_t zb = (size_t)pix*512;
    Zf[zb + c] = __float2half(interp);

    float w0 = wts[pix*3+0], w1 = wts[pix*3+1], w2 = wts[pix*3+2];
    size_t sb = (size_t)pix*CH + c;
    float blend = w0*__half2float(S0[sb]) + w1*__half2float(S1[sb])
                + w2*__half2float(S2[sb]);
    Zf[zb + 256 + c] = __float2half(blend);
}

// ----------------------------------------------------------------------------
// Host launch
// ----------------------------------------------------------------------------
extern "C" void kernel_launch(void* const* d_in, const int* in_sizes, int n_in,
                              void* d_out, int out_size)
{
    const float* x      = (const float*)d_in[0];
    const float* attn_w = (const float*)d_in[1];
    const float* attn_b = (const float*)d_in[2];
    const float* edge_w = (const float*)d_in[3];
    const float* mlp_w1 = (const float*)d_in[4];
    const float* mlp_b1 = (const float*)d_in[5];
    const float* mlp_w2 = (const float*)d_in[6];
    const float* mlp_b2 = (const float*)d_in[7];
    const float* dl_w   = (const float*)d_in[8];
    const float* dl_b   = (const float*)d_in[9];
    const float* ax_w   = (const float*)d_in[10];
    const float* ax_b   = (const float*)d_in[11];
    const float* g_sh   = (const float*)d_in[12];
    const float* g_bi   = (const float*)d_in[13];
    const float* sq_w   = (const float*)d_in[14];
    const float* sq_b   = (const float*)d_in[15];
    float* out = (float*)d_out;

    __half *QKVh, *CTXh, *Sh, *Xf, *Zf, *Wf, *XDLf;
    float *T9b, *EDGEb, *WTSb, *AQb, *AKb, *AVb, *XGb;
    cudaGetSymbolAddress((void**)&QKVh, g_QKV);
    cudaGetSymbolAddress((void**)&CTXh, g_CTX);
    cudaGetSymbolAddress((void**)&Sh,   g_S);
    cudaGetSymbolAddress((void**)&Xf,   g_xf);
    cudaGetSymbolAddress((void**)&Zf,   g_Zf);
    cudaGetSymbolAddress((void**)&Wf,   g_Wf);
    cudaGetSymbolAddress((void**)&XDLf, g_xdlf);
    cudaGetSymbolAddress((void**)&T9b,  g_t9);
    cudaGetSymbolAddress((void**)&EDGEb,g_edge);
    cudaGetSymbolAddress((void**)&WTSb, g_wts);
    cudaGetSymbolAddress((void**)&AQb,  g_aQ);
    cudaGetSymbolAddress((void**)&AKb,  g_aK);
    cudaGetSymbolAddress((void**)&AVb,  g_aV);
    cudaGetSymbolAddress((void**)&XGb,  g_xg);

    const int GH = 2 * SMH_BUF;   // 40960 bytes (< 48K default, no attribute)

    // ---- conversions ----
    convw_t16<<<15*65536/256, 256>>>(attn_w, ax_w, Wf);
    convw_sq16<<<256*512/256, 256>>>(sq_w, Wf + WF_SQ);
    xtoh_kernel<<<NTOK*CH/4/256, 256>>>((const float4*)x, Xf);

    // ---- fused QKV projections: 9 matrices, one launch ----
    {
        TilesT<__half, 9> Tq;
        for (int br = 0; br < 3; br++)
            for (int j = 0; j < 3; j++) {
                const int s = br*3 + j;
                Tq.t[s].a = Xf;
                Tq.t[s].b = Wf + (size_t)(br*4 + j)*65536;
                Tq.t[s].bias = attn_b + (br*4 + j)*CH;
                Tq.t[s].out  = QKVh + (size_t)s*NTOK*CH;
            }
        gemm_h<<<dim3(18, NTOK/128), 256, GH>>>(Tq, 256);
    }

    // ---- window attention per branch ----
    const dim3 attn_grid(1024, 4);
    winattn_kernel<2><<<attn_grid, 128>>>(
        (const uint4*)(QKVh + (size_t)0*NTOK*CH),
        (const uint4*)(QKVh + (size_t)1*NTOK*CH),
        (const uint4*)(QKVh + (size_t)2*NTOK*CH),
        (uint4*)(CTXh + (size_t)0*NTOK*CH));
    winattn_kernel<4><<<attn_grid, 128>>>(
        (const uint4*)(QKVh + (size_t)3*NTOK*CH),
        (const uint4*)(QKVh + (size_t)4*NTOK*CH),
        (const uint4*)(QKVh + (size_t)5*NTOK*CH),
        (uint4*)(CTXh + (size_t)1*NTOK*CH));
    winattn_kernel<8><<<attn_grid, 128>>>(
        (const uint4*)(QKVh + (size_t)6*NTOK*CH),
        (const uint4*)(QKVh + (size_t)7*NTOK*CH),
        (const uint4*)(QKVh + (size_t)8*NTOK*CH),
        (uint4*)(CTXh + (size_t)2*NTOK*CH));

    // ---- fused out-projections: 3 matrices ----
    {
        TilesT<__half, 3> To;
        for (int br = 0; br < 3; br++) {
            To.t[br].a = CTXh + (size_t)br*NTOK*CH;
            To.t[br].b = Wf + (size_t)(br*4 + 3)*65536;
            To.t[br].bias = attn_b + (br*4 + 3)*CH;
            To.t[br].out  = Sh + (size_t)br*NTOK*CH;
        }
        gemm_h<<<dim3(6, NTOK/128), 256, GH>>>(To, 256);
    }

    // ---- edge selector ----
    conv9_kernel<<<NTOK/8, 256>>>(x, edge_w, T9b);
    edge_stencil_kernel<<<NTOK/256, 256>>>(T9b, EDGEb);
    wts_kernel<<<NTOK/256, 256>>>(EDGEb, mlp_w1, mlp_b1, mlp_w2, mlp_b2, WTSb);

    // ---- DlightConv ----
    dlight_kernel<<<NDTOK, 256>>>(Sh + (size_t)1*NTOK*CH, dl_w, dl_b, XDLf);

    // ---- axial projections: 3 matrices, fp32 out ----
    {
        TilesT<float, 3> Ta;
        float* aqkv[3] = {AQb, AKb, AVb};
        for (int m = 0; m < 3; m++) {
            Ta.t[m].a = XDLf;
            Ta.t[m].b = Wf + WF_AX + (size_t)m*65536;
            Ta.t[m].bias = ax_b + m*CH;
            Ta.t[m].out  = aqkv[m];
        }
        gemm_h<<<dim3(6, NDTOK/128), 256, GH>>>(Ta, 256);
    }

    // ---- axial attention ----
    axial_kernel<<<BSZ*PP, 256>>>(AQb, AKb, AVb, g_sh, g_bi, XGb, 0);
    axial_kernel<<<BSZ*PP, 256>>>(AQb, AKb, AVb, g_sh, g_bi, XGb, 1);

    // ---- Z build + final projection ----
    zbuild_kernel<<<NTOK, 256>>>(XGb,
                                 Sh + (size_t)0*NTOK*CH,
                                 Sh + (size_t)1*NTOK*CH,
                                 Sh + (size_t)2*NTOK*CH,
                                 WTSb, Zf);
    {
        TilesT<float, 1> Tf;
        Tf.t[0].a = Zf;
        Tf.t[0].b = Wf + WF_SQ;
        Tf.t[0].bias = sq_b;
        Tf.t[0].out  = out;
        gemm_h<<<dim3(2, NTOK/128), 256, GH>>>(Tf, 512);
    }
}